// round 3
// baseline (speedup 1.0000x reference)
#include <cuda_runtime.h>
#include <cuda_bf16.h>

#define HDIM   256
#define GDIM   1024      // 4*H
#define BATCH  64
#define SEQ    512
#define NRD    10        // 5 branches * 2 directions
#define NBR    5
#define EDIM   300
#define ADIM   512       // 2*H

#define NSCAN      80        // 10 recs x 8 j-slices
#define NTILES     40960u    // 256 spairs x 10 recs x 16 ntiles
#define TILES_PER_SLOT 160u

typedef unsigned long long ull;

// ---------------- scratch (device globals; no allocation allowed) ----------------
__device__ float g_P [335544320];   // [NRD][SEQ][BATCH][GDIM]
__device__ float g_HS[ 83886080];   // [NRD][SEQ][BATCH][HDIM]
__device__ float g_H [2][NRD][BATCH][HDIM];
__device__ float g_ATT[NBR][BATCH][ADIM];
__device__ float g_logit[NBR][BATCH][SEQ];
__device__ float g_attw [NBR][BATCH][SEQ];
__device__ unsigned g_cnt[NRD];
__device__ unsigned g_ready[NRD * 256];   // per (rec, spair): #ntiles done (target 16)
__device__ unsigned g_tilectr;

__device__ __forceinline__ float fsigm(float x) { return 1.0f / (1.0f + __expf(-x)); }
__device__ __forceinline__ float ftanh(float x) { return 1.0f - 2.0f / (__expf(2.0f * x) + 1.0f); }

__device__ __forceinline__ ull pk2(float lo, float hi) {
    ull r; asm("mov.b64 %0, {%1, %2};" : "=l"(r) : "f"(lo), "f"(hi)); return r;
}
__device__ __forceinline__ ull dup2(float v) { return pk2(v, v); }
__device__ __forceinline__ void fma2(ull& d, ull a, ull b) {
    asm("fma.rn.f32x2 %0, %1, %2, %3;" : "=l"(d) : "l"(a), "l"(b), "l"(d));
}
__device__ __forceinline__ void unpk2(ull v, float& lo, float& hi) {
    asm("mov.b64 {%0, %1}, %2;" : "=f"(lo), "=f"(hi) : "l"(v));
}

// ---------------- init -----------------------------------------------------------
__global__ void k_init() {
    int idx = blockIdx.x * blockDim.x + threadIdx.x;
    if (idx < 2 * NRD * BATCH * HDIM) ((float*)g_H)[idx] = 0.0f;
    if (idx < NBR * BATCH * SEQ)      ((float*)g_logit)[idx] = 0.0f;
    if (idx < NRD)                    g_cnt[idx] = 0u;
    if (idx < NRD * 256)              g_ready[idx] = 0u;
    if (idx == 0)                     g_tilectr = 0u;
}

// ================= fused persistent kernel: producers + recurrent scan ===========
// blocks 0..79: scan (rec = bid>>3, j-slice = bid&7), smem = Whh slice + h stage
// blocks 80+ : GEMM workers, tile queue ordered for producer-consumer pacing
#define SCAN_SMEM ((256 * 132 + 256 * 68) * 4)

__global__ void __launch_bounds__(256, 1)
k_fused(const int* __restrict__ x, const float* __restrict__ emb,
        const float* __restrict__ Wih_f, const float* __restrict__ Wih_b,
        const float* __restrict__ bih_f, const float* __restrict__ bhh_f,
        const float* __restrict__ bih_b, const float* __restrict__ bhh_b,
        const float* __restrict__ Whh_f, const float* __restrict__ Whh_b) {
    extern __shared__ float sm[];
    int tid = threadIdx.x;

    if (blockIdx.x < NSCAN) {
        // ---------------- scan path ----------------
        float* swT = sm;                 // [256 k][132]: slot gate*32 + 2*jl + half
        float* sh  = sm + 256 * 132;     // [256 k][68]:  h transposed

        int rd = blockIdx.x >> 3;
        int blk = blockIdx.x & 7;
        int j0 = blk * 32;
        int branch = rd >> 1, dir = rd & 1;
        const float* W = (dir ? Whh_b : Whh_f) + (size_t)branch * GDIM * HDIM;

        for (int e = tid; e < 128 * HDIM; e += 256) {
            int r = e >> 8;
            int k = e & 255;
            int gate = r >> 5, jl = r & 31;
            int slot = gate * 32 + 2 * (jl & 15) + (jl >> 4);
            swT[k * 132 + slot] = W[(size_t)(gate * HDIM + j0 + jl) * HDIM + k];
        }
        int bt = tid >> 4, rt = tid & 15;
        int b0 = bt * 4;
        float c[2][4];
#pragma unroll
        for (int a = 0; a < 2; a++)
#pragma unroll
            for (int bb = 0; bb < 4; bb++) c[a][bb] = 0.0f;
        __syncthreads();

        for (int t = 0; t < SEQ; ++t) {
            int sidx = dir ? (SEQ - 1 - t) : t;
            int spair = sidx >> 1;
            // wait until producers finished this P row-pair
            if (tid == 0) {
                while (atomicAdd(&g_ready[rd * 256 + spair], 0u) < 16u) __nanosleep(128);
            }
            __syncthreads();

            const float* Pb = g_P + ((size_t)rd * SEQ + sidx) * BATCH * GDIM;
            ull acc[4][4];   // issue these LDGs early; latency hidden by h staging
#pragma unroll
            for (int g = 0; g < 4; g++)
#pragma unroll
                for (int bb = 0; bb < 4; bb++) {
                    const float* pp = Pb + (size_t)(b0 + bb) * GDIM + g * HDIM + j0 + rt;
                    acc[g][bb] = pk2(pp[0], pp[16]);
                }

            int par = t & 1;
            const float* Hin = &g_H[par][rd][0][0];
            for (int e = tid; e < BATCH * HDIM; e += 256) {
                int b = e >> 8, k = e & 255;
                sh[k * 68 + b] = __ldcv(&Hin[e]);   // bypass L1: peers rewrote it
            }
            __syncthreads();

#pragma unroll 4
            for (int k = 0; k < HDIM; k++) {
                float4 hb4 = *(const float4*)&sh[k * 68 + b0];
                ull hd[4] = {dup2(hb4.x), dup2(hb4.y), dup2(hb4.z), dup2(hb4.w)};
#pragma unroll
                for (int g = 0; g < 4; g++) {
                    ull wp = *(const ull*)&swT[k * 132 + g * 32 + 2 * rt];
#pragma unroll
                    for (int bb = 0; bb < 4; bb++) fma2(acc[g][bb], wp, hd[bb]);
                }
            }
            float* Hout = &g_H[par ^ 1][rd][0][0];
            float hr[2][4];
#pragma unroll
            for (int bb = 0; bb < 4; bb++) {
                float i0, i1, f0, f1, gg0, gg1, o0, o1;
                unpk2(acc[0][bb], i0, i1);
                unpk2(acc[1][bb], f0, f1);
                unpk2(acc[2][bb], gg0, gg1);
                unpk2(acc[3][bb], o0, o1);
                float cn0 = fsigm(f0) * c[0][bb] + fsigm(i0) * ftanh(gg0);
                float cn1 = fsigm(f1) * c[1][bb] + fsigm(i1) * ftanh(gg1);
                c[0][bb] = cn0; c[1][bb] = cn1;
                float h0 = fsigm(o0) * ftanh(cn0);
                float h1 = fsigm(o1) * ftanh(cn1);
                hr[0][bb] = h0; hr[1][bb] = h1;
                int j = j0 + rt;
                Hout[(b0 + bb) * HDIM + j]      = h0;
                Hout[(b0 + bb) * HDIM + j + 16] = h1;
            }
            // inter-block step barrier (per recurrence)
            __syncthreads();
            if (tid == 0) {
                __threadfence();
                atomicAdd(&g_cnt[rd], 1u);
                unsigned target = 8u * (unsigned)(t + 1);
                while (atomicAdd(&g_cnt[rd], 0u) < target) __nanosleep(64);
            }
            __syncthreads();
            // HS stores off the critical path (only consumed after kernel end)
            float* HSo = g_HS + ((size_t)rd * SEQ + sidx) * BATCH * HDIM;
#pragma unroll
            for (int bb = 0; bb < 4; bb++) {
                int j = j0 + rt;
                HSo[(size_t)(b0 + bb) * HDIM + j]      = hr[0][bb];
                HSo[(size_t)(b0 + bb) * HDIM + j + 16] = hr[1][bb];
            }
        }
    } else {
        // ---------------- worker path: P = emb[x] @ Wih.T + (bih+bhh) ------------
        float* As = sm;                          // [2][8][132]
        float* Bs = sm + 2 * 8 * 132;            // [2][8][68]
        int*   tok = (int*)(Bs + 2 * 8 * 68);    // [128]
        unsigned* tsh = (unsigned*)(tok + 128);
        int ty = tid >> 4, tx = tid & 15;

        while (true) {
            if (tid == 0) tsh[0] = atomicAdd(&g_tilectr, 1u);
            __syncthreads();
            unsigned tile = tsh[0];
            if (tile >= NTILES) break;
            unsigned slot = tile / TILES_PER_SLOT;     // 0..255
            unsigned rem  = tile % TILES_PER_SLOT;
            int rr = (int)(rem >> 4);                  // rec 0..9
            int nt = (int)(rem & 15u);
            int dir = rr & 1, branch = rr >> 1;
            int spair = dir ? (255 - (int)slot) : (int)slot;
            int m0 = spair * 128, n0 = nt * 64;
            const float* Wih = (dir ? Wih_b : Wih_f) + (size_t)branch * GDIM * EDIM;
            const float* bi  = (dir ? bih_b : bih_f) + branch * GDIM;
            const float* bh  = (dir ? bhh_b : bhh_f) + branch * GDIM;

            if (tid < 128) {
                int m = m0 + tid;
                int s = m >> 6, b = m & 63;
                tok[tid] = x[b * SEQ + s];
            }
            __syncthreads();

            ull acc[4][4];
#pragma unroll
            for (int p = 0; p < 4; p++)
#pragma unroll
                for (int j = 0; j < 4; j++) acc[p][j] = 0ull;

            // stage k0 = 0 into buf 0
            {
                float* Ad = As;  float* Bd = Bs;
#pragma unroll
                for (int q = 0; q < 4; q++) {
                    int e = tid + q * 256;
                    int mm = e >> 3, kk = e & 7;
                    Ad[kk * 132 + mm] = emb[(size_t)tok[mm] * EDIM + kk];
                }
#pragma unroll
                for (int q = 0; q < 2; q++) {
                    int e = tid + q * 256;
                    int nn = e >> 3, kk = e & 7;
                    Bd[kk * 68 + nn] = Wih[(size_t)(n0 + nn) * EDIM + kk];
                }
            }
            __syncthreads();

            int buf = 0;
            for (int k0 = 0; k0 < 304; k0 += 8) {
                if (k0 + 8 < 304) {
                    float* Ad = As + (buf ^ 1) * 1056;
                    float* Bd = Bs + (buf ^ 1) * 544;
                    int kb = k0 + 8;
#pragma unroll
                    for (int q = 0; q < 4; q++) {
                        int e = tid + q * 256;
                        int mm = e >> 3, kk = e & 7;
                        int k = kb + kk;
                        Ad[kk * 132 + mm] = (k < EDIM) ? emb[(size_t)tok[mm] * EDIM + k] : 0.0f;
                    }
#pragma unroll
                    for (int q = 0; q < 2; q++) {
                        int e = tid + q * 256;
                        int nn = e >> 3, kk = e & 7;
                        int k = kb + kk;
                        Bd[kk * 68 + nn] = (k < EDIM) ? Wih[(size_t)(n0 + nn) * EDIM + k] : 0.0f;
                    }
                }
                const float* Ac = As + buf * 1056;
                const float* Bc = Bs + buf * 544;
#pragma unroll
                for (int kk = 0; kk < 8; kk++) {
                    ull ap[4];
#pragma unroll
                    for (int p = 0; p < 4; p++) ap[p] = *(const ull*)&Ac[kk * 132 + ty * 8 + 2 * p];
                    float4 bv = *(const float4*)&Bc[kk * 68 + tx * 4];
                    ull bd[4] = {dup2(bv.x), dup2(bv.y), dup2(bv.z), dup2(bv.w)};
#pragma unroll
                    for (int p = 0; p < 4; p++)
#pragma unroll
                        for (int j = 0; j < 4; j++) fma2(acc[p][j], ap[p], bd[j]);
                }
                __syncthreads();
                buf ^= 1;
            }
#pragma unroll
            for (int p = 0; p < 4; p++) {
#pragma unroll
                for (int q = 0; q < 2; q++) {
                    int m = m0 + ty * 8 + 2 * p + q;
                    int s = m >> 6, b = m & 63;
                    float* Pp = g_P + (((size_t)rr * SEQ + s) * BATCH + b) * GDIM + n0;
#pragma unroll
                    for (int j = 0; j < 4; j++) {
                        int n = tx * 4 + j;
                        float lo, hi; unpk2(acc[p][j], lo, hi);
                        float v = q ? hi : lo;
                        Pp[n] = v + bi[n0 + n] + bh[n0 + n];
                    }
                }
            }
            __syncthreads();
            if (tid == 0) {
                __threadfence();
                atomicAdd(&g_ready[rr * 256 + spair], 1u);
            }
        }
    }
}

// ---------------- phase 3a: attention logits (f32x2 GEMM, fused tanh+watt) -------
__global__ void k_logits(const float* __restrict__ Wa, const float* __restrict__ ba,
                         const float* __restrict__ watt) {
    __shared__ __align__(16) float As[8][132];
    __shared__ __align__(16) float Bs[8][68];
    __shared__ float red[128][17];
    int mtile = blockIdx.x, ntile = blockIdx.y, br = blockIdx.z;
    const float* W = Wa + (size_t)br * ADIM * ADIM;
    int tid = threadIdx.x;
    int m0 = mtile * 128, n0 = ntile * 64;
    int ty = tid >> 4, tx = tid & 15;
    ull acc[4][4];
#pragma unroll
    for (int p = 0; p < 4; p++)
#pragma unroll
        for (int j = 0; j < 4; j++) acc[p][j] = 0ull;

    for (int k0 = 0; k0 < ADIM; k0 += 8) {
        for (int e = tid; e < 1024; e += 256) {
            int mm = e >> 3, kk = e & 7;
            int k = k0 + kk;
            int m = m0 + mm;
            int s = m >> 6, b = m & 63;
            int rdh = 2 * br + (k >> 8);
            int dd = k & 255;
            As[kk][mm] = g_HS[(((size_t)rdh * SEQ + s) * BATCH + b) * HDIM + dd];
        }
        for (int e = tid; e < 512; e += 256) {
            int nn = e >> 3, kk = e & 7;
            Bs[kk][nn] = W[(size_t)(n0 + nn) * ADIM + k0 + kk];
        }
        __syncthreads();
#pragma unroll
        for (int kk = 0; kk < 8; kk++) {
            ull ap[4];
#pragma unroll
            for (int p = 0; p < 4; p++) ap[p] = *(const ull*)&As[kk][ty * 8 + 2 * p];
            float4 bv = *(const float4*)&Bs[kk][tx * 4];
            ull bd[4] = {dup2(bv.x), dup2(bv.y), dup2(bv.z), dup2(bv.w)};
#pragma unroll
            for (int p = 0; p < 4; p++)
#pragma unroll
                for (int j = 0; j < 4; j++) fma2(acc[p][j], ap[p], bd[j]);
        }
        __syncthreads();
    }
#pragma unroll
    for (int p = 0; p < 4; p++) {
#pragma unroll
        for (int q = 0; q < 2; q++) {
            float part = 0.0f;
#pragma unroll
            for (int j = 0; j < 4; j++) {
                int n = n0 + tx * 4 + j;
                float lo, hi; unpk2(acc[p][j], lo, hi);
                float v = q ? hi : lo;
                float u = ftanh(v + ba[br * ADIM + n]);
                part += u * watt[br * ADIM + n];
            }
            red[ty * 8 + 2 * p + q][tx] = part;
        }
    }
    __syncthreads();
    if (tid < 128) {
        float sv = 0.0f;
#pragma unroll
        for (int qq = 0; qq < 16; qq++) sv += red[tid][qq];
        int m = m0 + tid;
        int s = m >> 6, b = m & 63;
        atomicAdd(&g_logit[br][b][s], sv);
    }
}

// ---------------- phase 3b: softmax over S -------------------------------------
__global__ void k_softmax() {
    int br = blockIdx.x >> 6, b = blockIdx.x & 63;
    __shared__ float red[256];
    const float* L = &g_logit[br][b][0];
    int tid = threadIdx.x;
    float m1 = fmaxf(L[tid], L[tid + 256]);
    red[tid] = m1; __syncthreads();
    for (int o = 128; o > 0; o >>= 1) { if (tid < o) red[tid] = fmaxf(red[tid], red[tid + o]); __syncthreads(); }
    float mx = red[0]; __syncthreads();
    float e0 = __expf(L[tid] - mx), e1 = __expf(L[tid + 256] - mx);
    red[tid] = e0 + e1; __syncthreads();
    for (int o = 128; o > 0; o >>= 1) { if (tid < o) red[tid] += red[tid + o]; __syncthreads(); }
    float inv = 1.0f / red[0];
    g_attw[br][b][tid] = e0 * inv;
    g_attw[br][b][tid + 256] = e1 * inv;
}

// ---------------- phase 3c: attention-weighted sum ------------------------------
__global__ void k_attsum() {
    int b = blockIdx.x, br = blockIdx.y;
    int d = threadIdx.x;   // 512 threads
    __shared__ float aw[512];
    aw[d] = g_attw[br][b][d];
    __syncthreads();
    int rdh = (d < HDIM) ? (2 * br) : (2 * br + 1);
    int dd = d & 255;
    const float* base = g_HS + (size_t)rdh * SEQ * BATCH * HDIM + (size_t)b * HDIM + dd;
    float a0 = 0.0f, a1 = 0.0f;
    for (int s = 0; s < SEQ; s += 2) {
        a0 = fmaf(aw[s],     base[(size_t)s * BATCH * HDIM], a0);
        a1 = fmaf(aw[s + 1], base[(size_t)(s + 1) * BATCH * HDIM], a1);
    }
    g_ATT[br][b][d] = a0 + a1;
}

// ---------------- phase 4: routed final FC --------------------------------------
__global__ void k_final(const int* __restrict__ z, const float* __restrict__ Wfc,
                        const float* __restrict__ bfc, float* __restrict__ out) {
    int b = blockIdx.x;
    int tid = threadIdx.x;   // 256
    int zb = z[b];
    __shared__ float red0[256], red1[256];
    float a0 = 0.0f, a1 = 0.0f;
    for (int k = tid; k < 1024; k += 256) {
        float v = (k < 512) ? g_ATT[zb + 1][b][k] : g_ATT[0][b][k - 512];
        a0 = fmaf(v, Wfc[k], a0);
        a1 = fmaf(v, Wfc[1024 + k], a1);
    }
    red0[tid] = a0; red1[tid] = a1; __syncthreads();
    for (int o = 128; o > 0; o >>= 1) {
        if (tid < o) { red0[tid] += red0[tid + o]; red1[tid] += red1[tid + o]; }
        __syncthreads();
    }
    if (tid == 0) {
        out[b * 2 + 0] = red0[0] + bfc[0];
        out[b * 2 + 1] = red1[0] + bfc[1];
    }
}

// ---------------- copy general + specifics into d_out ---------------------------
__global__ void k_copyout(float* __restrict__ out) {
    int idx = blockIdx.x * blockDim.x + threadIdx.x;
    const float* A = &g_ATT[0][0][0];
    if (idx < NBR * BATCH * ADIM) out[128 + idx] = A[idx];
}

// ---------------- launcher -------------------------------------------------------
extern "C" void kernel_launch(void* const* d_in, const int* in_sizes, int n_in,
                              void* d_out, int out_size) {
    const int*   x     = (const int*)  d_in[0];
    const int*   z     = (const int*)  d_in[1];
    const float* emb   = (const float*)d_in[2];
    const float* Wih_f = (const float*)d_in[3];
    const float* Whh_f = (const float*)d_in[4];
    const float* bih_f = (const float*)d_in[5];
    const float* bhh_f = (const float*)d_in[6];
    const float* Wih_b = (const float*)d_in[7];
    const float* Whh_b = (const float*)d_in[8];
    const float* bih_b = (const float*)d_in[9];
    const float* bhh_b = (const float*)d_in[10];
    const float* Wa    = (const float*)d_in[11];
    const float* ba    = (const float*)d_in[12];
    const float* watt  = (const float*)d_in[13];
    const float* Wfc   = (const float*)d_in[14];
    const float* bfc   = (const float*)d_in[15];
    float* out = (float*)d_out;

    cudaFuncSetAttribute(k_fused, cudaFuncAttributeMaxDynamicSharedMemorySize, SCAN_SMEM);

    k_init<<<1280, 256>>>();
    k_fused<<<152, 256, SCAN_SMEM>>>(x, emb, Wih_f, Wih_b, bih_f, bhh_f, bih_b, bhh_b,
                                     Whh_f, Whh_b);
    k_logits<<<dim3(256, 8, 5), 256>>>(Wa, ba, watt);
    k_softmax<<<320, 256>>>();
    k_attsum<<<dim3(64, 5), 512>>>();
    k_final<<<64, 256>>>(z, Wfc, bfc, out);
    k_copyout<<<640, 256>>>(out);
}

// round 5
// speedup vs baseline: 1.8657x; 1.8657x over previous
#include <cuda_runtime.h>
#include <cuda_bf16.h>

#define HDIM   256
#define GDIM   1024      // 4*H
#define BATCH  64
#define SEQ    512
#define NRD    10        // 5 branches * 2 directions
#define NBR    5
#define EDIM   300
#define ADIM   512       // 2*H

typedef unsigned long long ull;
typedef unsigned int u32;

// ---------------- scratch (device globals; no allocation allowed) ----------------
__device__ float g_P [335544320];   // [NRD][SEQ][BATCH][GDIM]
__device__ float g_HS[ 83886080];   // [NRD][SEQ][BATCH][HDIM]
__device__ float g_H [2][NRD][BATCH][HDIM];
__device__ float g_ATT[NBR][BATCH][ADIM];
__device__ float g_logit[NBR][BATCH][SEQ];
__device__ float g_attw [NBR][BATCH][SEQ];
__device__ unsigned g_cnt[NRD];

__device__ __forceinline__ float fsigm(float x) { return 1.0f / (1.0f + __expf(-x)); }
__device__ __forceinline__ float ftanh(float x) { return 1.0f - 2.0f / (__expf(2.0f * x) + 1.0f); }

__device__ __forceinline__ ull pk2(float lo, float hi) {
    ull r; asm("mov.b64 %0, {%1, %2};" : "=l"(r) : "f"(lo), "f"(hi)); return r;
}
__device__ __forceinline__ ull dup2(float v) { return pk2(v, v); }
__device__ __forceinline__ void fma2(ull& d, ull a, ull b) {
    asm("fma.rn.f32x2 %0, %1, %2, %3;" : "=l"(d) : "l"(a), "l"(b), "l"(d));
}
__device__ __forceinline__ void unpk2(ull v, float& lo, float& hi) {
    asm("mov.b64 {%0, %1}, %2;" : "=f"(lo), "=f"(hi) : "l"(v));
}

// bf16 2-term split of a float pair -> (hi word, lo word) each packing 2 bf16
__device__ __forceinline__ ull split2(float2 v) {
    __nv_bfloat162 h = __floats2bfloat162_rn(v.x, v.y);
    float r0 = v.x - __bfloat162float(h.x);
    float r1 = v.y - __bfloat162float(h.y);
    __nv_bfloat162 l = __floats2bfloat162_rn(r0, r1);
    u32 hw = *(u32*)&h;
    u32 lw = *(u32*)&l;
    return (ull)hw | ((ull)lw << 32);
}

#define MMA_BF16(c, a, b) \
    asm volatile("mma.sync.aligned.m16n8k16.row.col.f32.bf16.bf16.f32 " \
                 "{%0,%1,%2,%3}, {%4,%5,%6,%7}, {%8,%9}, {%0,%1,%2,%3};" \
                 : "+f"((c)[0]), "+f"((c)[1]), "+f"((c)[2]), "+f"((c)[3]) \
                 : "r"((a)[0]), "r"((a)[1]), "r"((a)[2]), "r"((a)[3]), \
                   "r"((b)[0]), "r"((b)[1]))

// ---------------- init -----------------------------------------------------------
__global__ void k_init() {
    int idx = blockIdx.x * blockDim.x + threadIdx.x;
    if (idx < 2 * NRD * BATCH * HDIM) ((float*)g_H)[idx] = 0.0f;
    if (idx < NBR * BATCH * SEQ)      ((float*)g_logit)[idx] = 0.0f;
    if (idx < NRD)                    g_cnt[idx] = 0u;
}

// ---------------- phase 1: P = emb[x] @ Wih.T + (bih+bhh)  [bf16-split HMMA] ------
// block: 128m x 64n, 256 threads = 8 warps (4m x 2n), warp: 32m x 32n
__global__ void k_inputproj(const int* __restrict__ x, const float* __restrict__ emb,
                            const float* __restrict__ Wih_f, const float* __restrict__ Wih_b,
                            const float* __restrict__ bih_f, const float* __restrict__ bhh_f,
                            const float* __restrict__ bih_b, const float* __restrict__ bhh_b) {
    __shared__ __align__(8) u32 As_s[128 * 20];   // [m][kp*2 + {hi,lo}]
    __shared__ __align__(8) u32 Bs_s[64 * 20];
    __shared__ int tok[128];
    int mtile = blockIdx.x, ntile = blockIdx.y, rd = blockIdx.z;
    int branch = rd >> 1, dir = rd & 1;
    const float* Wih = (dir ? Wih_b : Wih_f) + (size_t)branch * GDIM * EDIM;
    const float* bi  = (dir ? bih_b : bih_f) + branch * GDIM;
    const float* bh  = (dir ? bhh_b : bhh_f) + branch * GDIM;
    int tid = threadIdx.x;
    int m0 = mtile * 128, n0 = ntile * 64;
    if (tid < 128) {
        int m = m0 + tid;
        int s = m >> 6, b = m & 63;
        tok[tid] = x[b * SEQ + s];
    }
    int lane = tid & 31, wid = tid >> 5;
    int g = lane >> 2, tg = lane & 3;
    int wm = wid & 3, wn = wid >> 2;
    int mbase = wm * 32, nbase = wn * 32;
    float C[2][4][4];
#pragma unroll
    for (int mt = 0; mt < 2; mt++)
#pragma unroll
        for (int nt = 0; nt < 4; nt++)
#pragma unroll
            for (int q = 0; q < 4; q++) C[mt][nt][q] = 0.0f;
    __syncthreads();

    for (int k0 = 0; k0 < 304; k0 += 16) {
        // stage A: 128 m x 8 kpairs
#pragma unroll
        for (int i = 0; i < 4; i++) {
            int task = tid + i * 256;
            int m = task >> 3, kp = task & 7;
            int k = k0 + 2 * kp;
            float2 v = (k < EDIM) ? *(const float2*)(emb + (size_t)tok[m] * EDIM + k)
                                  : make_float2(0.0f, 0.0f);
            *(ull*)&As_s[m * 20 + 2 * kp] = split2(v);
        }
        // stage B: 64 n x 8 kpairs
#pragma unroll
        for (int i = 0; i < 2; i++) {
            int task = tid + i * 256;
            int n = task >> 3, kp = task & 7;
            int k = k0 + 2 * kp;
            float2 v = (k < EDIM) ? *(const float2*)(Wih + (size_t)(n0 + n) * EDIM + k)
                                  : make_float2(0.0f, 0.0f);
            *(ull*)&Bs_s[n * 20 + 2 * kp] = split2(v);
        }
        __syncthreads();

        u32 Ahi[2][4], Alo[2][4], Bhi[4][2], Blo[4][2];
#pragma unroll
        for (int mt = 0; mt < 2; mt++) {
            int r0 = mbase + mt * 16 + g;
            ull v0 = *(const ull*)&As_s[r0 * 20 + 2 * tg];
            ull v1 = *(const ull*)&As_s[(r0 + 8) * 20 + 2 * tg];
            ull v2 = *(const ull*)&As_s[r0 * 20 + 2 * (tg + 4)];
            ull v3 = *(const ull*)&As_s[(r0 + 8) * 20 + 2 * (tg + 4)];
            Ahi[mt][0] = (u32)v0; Alo[mt][0] = (u32)(v0 >> 32);
            Ahi[mt][1] = (u32)v1; Alo[mt][1] = (u32)(v1 >> 32);
            Ahi[mt][2] = (u32)v2; Alo[mt][2] = (u32)(v2 >> 32);
            Ahi[mt][3] = (u32)v3; Alo[mt][3] = (u32)(v3 >> 32);
        }
#pragma unroll
        for (int nt = 0; nt < 4; nt++) {
            int n = nbase + nt * 8 + g;
            ull v0 = *(const ull*)&Bs_s[n * 20 + 2 * tg];
            ull v1 = *(const ull*)&Bs_s[n * 20 + 2 * (tg + 4)];
            Bhi[nt][0] = (u32)v0; Blo[nt][0] = (u32)(v0 >> 32);
            Bhi[nt][1] = (u32)v1; Blo[nt][1] = (u32)(v1 >> 32);
        }
#pragma unroll
        for (int mt = 0; mt < 2; mt++)
#pragma unroll
            for (int nt = 0; nt < 4; nt++) {
                MMA_BF16(C[mt][nt], Ahi[mt], Bhi[nt]);
                MMA_BF16(C[mt][nt], Ahi[mt], Blo[nt]);
                MMA_BF16(C[mt][nt], Alo[mt], Bhi[nt]);
            }
        __syncthreads();
    }
    // epilogue: add biases, store float2
#pragma unroll
    for (int mt = 0; mt < 2; mt++) {
#pragma unroll
        for (int rr = 0; rr < 2; rr++) {
            int m = m0 + mbase + mt * 16 + g + rr * 8;
            int s = m >> 6, b = m & 63;
            float* Pp = g_P + (((size_t)rd * SEQ + s) * BATCH + b) * GDIM + n0 + nbase;
#pragma unroll
            for (int nt = 0; nt < 4; nt++) {
                int nl = nt * 8 + 2 * tg;
                int nfull = n0 + nbase + nl;
                float2 o;
                o.x = C[mt][nt][rr * 2 + 0] + bi[nfull]     + bh[nfull];
                o.y = C[mt][nt][rr * 2 + 1] + bi[nfull + 1] + bh[nfull + 1];
                *(float2*)(Pp + nl) = o;
            }
        }
    }
}

// ---------------- phase 2: persistent recurrent scan (f32x2) — proven R2 version --
#define SCAN_SMEM ((256 * 132 + 256 * 68) * 4)

__global__ void k_scan(const float* __restrict__ Whh_f, const float* __restrict__ Whh_b) {
    extern __shared__ float sm[];
    float* swT = sm;                 // [256 k][132]: slot gate*32 + 2*jl + half
    float* sh  = sm + 256 * 132;     // [256 k][68]:  h transposed

    int rd = blockIdx.x >> 3;
    int blk = blockIdx.x & 7;
    int j0 = blk * 32;
    int branch = rd >> 1, dir = rd & 1;
    const float* W = (dir ? Whh_b : Whh_f) + (size_t)branch * GDIM * HDIM;
    int tid = threadIdx.x;

    for (int e = tid; e < 128 * HDIM; e += 256) {
        int r = e >> 8;
        int k = e & 255;
        int gate = r >> 5, jl = r & 31;
        int slot = gate * 32 + 2 * (jl & 15) + (jl >> 4);
        swT[k * 132 + slot] = W[(size_t)(gate * HDIM + j0 + jl) * HDIM + k];
    }
    int bt = tid >> 4, rt = tid & 15;
    int b0 = bt * 4;
    float c[2][4];
#pragma unroll
    for (int a = 0; a < 2; a++)
#pragma unroll
        for (int bb = 0; bb < 4; bb++) c[a][bb] = 0.0f;
    __syncthreads();

    for (int t = 0; t < SEQ; ++t) {
        int par = t & 1;
        const float* Hin = &g_H[par][rd][0][0];
        for (int e = tid; e < BATCH * HDIM; e += 256) {
            int b = e >> 8, k = e & 255;
            sh[k * 68 + b] = Hin[e];
        }
        __syncthreads();

        int sidx = dir ? (SEQ - 1 - t) : t;
        const float* Pb = g_P + ((size_t)rd * SEQ + sidx) * BATCH * GDIM;

        ull acc[4][4];
#pragma unroll
        for (int g = 0; g < 4; g++)
#pragma unroll
            for (int bb = 0; bb < 4; bb++) {
                const float* pp = Pb + (size_t)(b0 + bb) * GDIM + g * HDIM + j0 + rt;
                acc[g][bb] = pk2(pp[0], pp[16]);
            }
#pragma unroll 4
        for (int k = 0; k < HDIM; k++) {
            float4 hb4 = *(const float4*)&sh[k * 68 + b0];
            ull hd[4] = {dup2(hb4.x), dup2(hb4.y), dup2(hb4.z), dup2(hb4.w)};
#pragma unroll
            for (int g = 0; g < 4; g++) {
                ull wp = *(const ull*)&swT[k * 132 + g * 32 + 2 * rt];
#pragma unroll
                for (int bb = 0; bb < 4; bb++) fma2(acc[g][bb], wp, hd[bb]);
            }
        }
        float* Hout = &g_H[par ^ 1][rd][0][0];
        float* HSo = g_HS + ((size_t)rd * SEQ + sidx) * BATCH * HDIM;
#pragma unroll
        for (int bb = 0; bb < 4; bb++) {
            float i0, i1, f0, f1, gg0, gg1, o0, o1;
            unpk2(acc[0][bb], i0, i1);
            unpk2(acc[1][bb], f0, f1);
            unpk2(acc[2][bb], gg0, gg1);
            unpk2(acc[3][bb], o0, o1);
            float cn0 = fsigm(f0) * c[0][bb] + fsigm(i0) * ftanh(gg0);
            float cn1 = fsigm(f1) * c[1][bb] + fsigm(i1) * ftanh(gg1);
            c[0][bb] = cn0; c[1][bb] = cn1;
            float h0 = fsigm(o0) * ftanh(cn0);
            float h1 = fsigm(o1) * ftanh(cn1);
            int j = j0 + rt;
            Hout[(b0 + bb) * HDIM + j]      = h0;
            Hout[(b0 + bb) * HDIM + j + 16] = h1;
            HSo[(size_t)(b0 + bb) * HDIM + j]      = h0;
            HSo[(size_t)(b0 + bb) * HDIM + j + 16] = h1;
        }
        __threadfence();
        __syncthreads();
        if (tid == 0) {
            atomicAdd(&g_cnt[rd], 1u);
            unsigned target = 8u * (unsigned)(t + 1);
            while (atomicAdd(&g_cnt[rd], 0u) < target) __nanosleep(64);
            __threadfence();
        }
        __syncthreads();
    }
}

// ---------------- phase 3a: attention logits  [bf16-split HMMA, fused tanh+watt] --
__global__ void k_logits(const float* __restrict__ Wa, const float* __restrict__ ba,
                         const float* __restrict__ watt) {
    __shared__ __align__(8) u32 As_s[128 * 20];
    __shared__ __align__(8) u32 Bs_s[64 * 20];
    int mtile = blockIdx.x, ntile = blockIdx.y, br = blockIdx.z;
    const float* W = Wa + (size_t)br * ADIM * ADIM;
    int tid = threadIdx.x;
    int m0 = mtile * 128, n0 = ntile * 64;
    int lane = tid & 31, wid = tid >> 5;
    int g = lane >> 2, tg = lane & 3;
    int wm = wid & 3, wn = wid >> 2;
    int mbase = wm * 32, nbase = wn * 32;
    float C[2][4][4];
#pragma unroll
    for (int mt = 0; mt < 2; mt++)
#pragma unroll
        for (int nt = 0; nt < 4; nt++)
#pragma unroll
            for (int q = 0; q < 4; q++) C[mt][nt][q] = 0.0f;

    for (int k0 = 0; k0 < ADIM; k0 += 16) {
#pragma unroll
        for (int i = 0; i < 4; i++) {
            int task = tid + i * 256;
            int m = task >> 3, kp = task & 7;
            int k = k0 + 2 * kp;
            int mm = m0 + m;
            int s = mm >> 6, b = mm & 63;
            int rdh = 2 * br + (k >> 8);
            int dd = k & 255;
            float2 v = *(const float2*)(g_HS + (((size_t)rdh * SEQ + s) * BATCH + b) * HDIM + dd);
            *(ull*)&As_s[m * 20 + 2 * kp] = split2(v);
        }
#pragma unroll
        for (int i = 0; i < 2; i++) {
            int task = tid + i * 256;
            int n = task >> 3, kp = task & 7;
            int k = k0 + 2 * kp;
            float2 v = *(const float2*)(W + (size_t)(n0 + n) * ADIM + k);
            *(ull*)&Bs_s[n * 20 + 2 * kp] = split2(v);
        }
        __syncthreads();

        u32 Ahi[2][4], Alo[2][4], Bhi[4][2], Blo[4][2];
#pragma unroll
        for (int mt = 0; mt < 2; mt++) {
            int r0 = mbase + mt * 16 + g;
            ull v0 = *(const ull*)&As_s[r0 * 20 + 2 * tg];
            ull v1 = *(const ull*)&As_s[(r0 + 8) * 20 + 2 * tg];
            ull v2 = *(const ull*)&As_s[r0 * 20 + 2 * (tg + 4)];
            ull v3 = *(const ull*)&As_s[(r0 + 8) * 20 + 2 * (tg + 4)];
            Ahi[mt][0] = (u32)v0; Alo[mt][0] = (u32)(v0 >> 32);
            Ahi[mt][1] = (u32)v1; Alo[mt][1] = (u32)(v1 >> 32);
            Ahi[mt][2] = (u32)v2; Alo[mt][2] = (u32)(v2 >> 32);
            Ahi[mt][3] = (u32)v3; Alo[mt][3] = (u32)(v3 >> 32);
        }
#pragma unroll
        for (int nt = 0; nt < 4; nt++) {
            int n = nbase + nt * 8 + g;
            ull v0 = *(const ull*)&Bs_s[n * 20 + 2 * tg];
            ull v1 = *(const ull*)&Bs_s[n * 20 + 2 * (tg + 4)];
            Bhi[nt][0] = (u32)v0; Blo[nt][0] = (u32)(v0 >> 32);
            Bhi[nt][1] = (u32)v1; Blo[nt][1] = (u32)(v1 >> 32);
        }
#pragma unroll
        for (int mt = 0; mt < 2; mt++)
#pragma unroll
            for (int nt = 0; nt < 4; nt++) {
                MMA_BF16(C[mt][nt], Ahi[mt], Bhi[nt]);
                MMA_BF16(C[mt][nt], Ahi[mt], Blo[nt]);
                MMA_BF16(C[mt][nt], Alo[mt], Bhi[nt]);
            }
        __syncthreads();
    }
    // epilogue: u = tanh(c + ba), part = sum_n u*watt[n]; reduce over tg lanes
#pragma unroll
    for (int mt = 0; mt < 2; mt++) {
        float p0 = 0.0f, p1 = 0.0f;    // rows g, g+8
#pragma unroll
        for (int nt = 0; nt < 4; nt++) {
            int nfull = n0 + nbase + nt * 8 + 2 * tg;
            float ba0 = ba[br * ADIM + nfull],     wa0 = watt[br * ADIM + nfull];
            float ba1 = ba[br * ADIM + nfull + 1], wa1 = watt[br * ADIM + nfull + 1];
            p0 += ftanh(C[mt][nt][0] + ba0) * wa0 + ftanh(C[mt][nt][1] + ba1) * wa1;
            p1 += ftanh(C[mt][nt][2] + ba0) * wa0 + ftanh(C[mt][nt][3] + ba1) * wa1;
        }
        p0 += __shfl_xor_sync(0xffffffffu, p0, 1);
        p0 += __shfl_xor_sync(0xffffffffu, p0, 2);
        p1 += __shfl_xor_sync(0xffffffffu, p1, 1);
        p1 += __shfl_xor_sync(0xffffffffu, p1, 2);
        if (tg == 0) {
            int m = m0 + mbase + mt * 16 + g;
            int s = m >> 6, b = m & 63;
            atomicAdd(&g_logit[br][b][s], p0);
            int m2 = m + 8;
            int s2 = m2 >> 6, b2 = m2 & 63;
            atomicAdd(&g_logit[br][b2][s2], p1);
        }
    }
}

// ---------------- phase 3b: softmax over S -------------------------------------
__global__ void k_softmax() {
    int br = blockIdx.x >> 6, b = blockIdx.x & 63;
    __shared__ float red[256];
    const float* L = &g_logit[br][b][0];
    int tid = threadIdx.x;
    float m1 = fmaxf(L[tid], L[tid + 256]);
    red[tid] = m1; __syncthreads();
    for (int o = 128; o > 0; o >>= 1) { if (tid < o) red[tid] = fmaxf(red[tid], red[tid + o]); __syncthreads(); }
    float mx = red[0]; __syncthreads();
    float e0 = __expf(L[tid] - mx), e1 = __expf(L[tid + 256] - mx);
    red[tid] = e0 + e1; __syncthreads();
    for (int o = 128; o > 0; o >>= 1) { if (tid < o) red[tid] += red[tid + o]; __syncthreads(); }
    float inv = 1.0f / red[0];
    g_attw[br][b][tid] = e0 * inv;
    g_attw[br][b][tid + 256] = e1 * inv;
}

// ---------------- phase 3c: attention-weighted sum ------------------------------
__global__ void k_attsum() {
    int b = blockIdx.x, br = blockIdx.y;
    int d = threadIdx.x;   // 512 threads
    __shared__ float aw[512];
    aw[d] = g_attw[br][b][d];
    __syncthreads();
    int rdh = (d < HDIM) ? (2 * br) : (2 * br + 1);
    int dd = d & 255;
    const float* base = g_HS + (size_t)rdh * SEQ * BATCH * HDIM + (size_t)b * HDIM + dd;
    float a0 = 0.0f, a1 = 0.0f;
    for (int s = 0; s < SEQ; s += 2) {
        a0 = fmaf(aw[s],     base[(size_t)s * BATCH * HDIM], a0);
        a1 = fmaf(aw[s + 1], base[(size_t)(s + 1) * BATCH * HDIM], a1);
    }
    g_ATT[br][b][d] = a0 + a1;
}

// ---------------- phase 4: routed final FC --------------------------------------
__global__ void k_final(const int* __restrict__ z, const float* __restrict__ Wfc,
                        const float* __restrict__ bfc, float* __restrict__ out) {
    int b = blockIdx.x;
    int tid = threadIdx.x;   // 256
    int zb = z[b];
    __shared__ float red0[256], red1[256];
    float a0 = 0.0f, a1 = 0.0f;
    for (int k = tid; k < 1024; k += 256) {
        float v = (k < 512) ? g_ATT[zb + 1][b][k] : g_ATT[0][b][k - 512];
        a0 = fmaf(v, Wfc[k], a0);
        a1 = fmaf(v, Wfc[1024 + k], a1);
    }
    red0[tid] = a0; red1[tid] = a1; __syncthreads();
    for (int o = 128; o > 0; o >>= 1) {
        if (tid < o) { red0[tid] += red0[tid + o]; red1[tid] += red1[tid + o]; }
        __syncthreads();
    }
    if (tid == 0) {
        out[b * 2 + 0] = red0[0] + bfc[0];
        out[b * 2 + 1] = red1[0] + bfc[1];
    }
}

// ---------------- copy general + specifics into d_out ---------------------------
__global__ void k_copyout(float* __restrict__ out) {
    int idx = blockIdx.x * blockDim.x + threadIdx.x;
    const float* A = &g_ATT[0][0][0];
    if (idx < NBR * BATCH * ADIM) out[128 + idx] = A[idx];
}

// ---------------- launcher -------------------------------------------------------
extern "C" void kernel_launch(void* const* d_in, const int* in_sizes, int n_in,
                              void* d_out, int out_size) {
    const int*   x     = (const int*)  d_in[0];
    const int*   z     = (const int*)  d_in[1];
    const float* emb   = (const float*)d_in[2];
    const float* Wih_f = (const float*)d_in[3];
    const float* Whh_f = (const float*)d_in[4];
    const float* bih_f = (const float*)d_in[5];
    const float* bhh_f = (const float*)d_in[6];
    const float* Wih_b = (const float*)d_in[7];
    const float* Whh_b = (const float*)d_in[8];
    const float* bih_b = (const float*)d_in[9];
    const float* bhh_b = (const float*)d_in[10];
    const float* Wa    = (const float*)d_in[11];
    const float* ba    = (const float*)d_in[12];
    const float* watt  = (const float*)d_in[13];
    const float* Wfc   = (const float*)d_in[14];
    const float* bfc   = (const float*)d_in[15];
    float* out = (float*)d_out;

    cudaFuncSetAttribute(k_scan, cudaFuncAttributeMaxDynamicSharedMemorySize, SCAN_SMEM);

    k_init<<<1280, 256>>>();
    k_inputproj<<<dim3(256, 16, 10), 256>>>(x, emb, Wih_f, Wih_b, bih_f, bhh_f, bih_b, bhh_b);
    k_scan<<<80, 256, SCAN_SMEM>>>(Whh_f, Whh_b);
    k_logits<<<dim3(256, 8, 5), 256>>>(Wa, ba, watt);
    k_softmax<<<320, 256>>>();
    k_attsum<<<dim3(64, 5), 512>>>();
    k_final<<<64, 256>>>(z, Wfc, bfc, out);
    k_copyout<<<640, 256>>>(out);
}

// round 6
// speedup vs baseline: 2.6742x; 1.4333x over previous
#include <cuda_runtime.h>
#include <cuda_bf16.h>

#define HDIM   256
#define GDIM   1024      // 4*H
#define BATCH  64
#define SEQ    512
#define NRD    10        // 5 branches * 2 directions
#define NBR    5
#define EDIM   300
#define ADIM   512       // 2*H

typedef unsigned long long ull;
typedef unsigned int u32;

// ---------------- scratch (device globals; no allocation allowed) ----------------
__device__ float g_P [335544320];   // [NRD][SEQ][BATCH][GDIM]
__device__ float g_HS[ 83886080];   // [NRD][SEQ][BATCH][HDIM]
__device__ float g_H [2][NRD][BATCH][HDIM];
__device__ float g_ATT[NBR][BATCH][ADIM];
__device__ float g_logit[NBR][BATCH][SEQ];
__device__ float g_attw [NBR][BATCH][SEQ];
__device__ unsigned g_cnt[NRD];

__device__ __forceinline__ float fsigm(float x) { return 1.0f / (1.0f + __expf(-x)); }
__device__ __forceinline__ float ftanh(float x) { return 1.0f - 2.0f / (__expf(2.0f * x) + 1.0f); }

// bf16 2-term split of a float pair -> (hi word | lo word << 32)
__device__ __forceinline__ ull split2(float2 v) {
    __nv_bfloat162 h = __floats2bfloat162_rn(v.x, v.y);
    float r0 = v.x - __bfloat162float(h.x);
    float r1 = v.y - __bfloat162float(h.y);
    __nv_bfloat162 l = __floats2bfloat162_rn(r0, r1);
    u32 hw = *(u32*)&h;
    u32 lw = *(u32*)&l;
    return (ull)hw | ((ull)lw << 32);
}

#define MMA_BF16(c, a, b) \
    asm volatile("mma.sync.aligned.m16n8k16.row.col.f32.bf16.bf16.f32 " \
                 "{%0,%1,%2,%3}, {%4,%5,%6,%7}, {%8,%9}, {%0,%1,%2,%3};" \
                 : "+f"((c)[0]), "+f"((c)[1]), "+f"((c)[2]), "+f"((c)[3]) \
                 : "r"((a)[0]), "r"((a)[1]), "r"((a)[2]), "r"((a)[3]), \
                   "r"((b)[0]), "r"((b)[1]))

// ---------------- init -----------------------------------------------------------
__global__ void k_init() {
    int idx = blockIdx.x * blockDim.x + threadIdx.x;
    if (idx < 2 * NRD * BATCH * HDIM) ((float*)g_H)[idx] = 0.0f;
    if (idx < NBR * BATCH * SEQ)      ((float*)g_logit)[idx] = 0.0f;
    if (idx < NRD)                    g_cnt[idx] = 0u;
}

// ---------------- phase 1: P = emb[x] @ Wih.T + (bih+bhh)  [bf16-split HMMA] ------
__global__ void k_inputproj(const int* __restrict__ x, const float* __restrict__ emb,
                            const float* __restrict__ Wih_f, const float* __restrict__ Wih_b,
                            const float* __restrict__ bih_f, const float* __restrict__ bhh_f,
                            const float* __restrict__ bih_b, const float* __restrict__ bhh_b) {
    __shared__ __align__(8) u32 As_s[128 * 20];   // [m][kp*2 + {hi,lo}]
    __shared__ __align__(8) u32 Bs_s[64 * 20];
    __shared__ int tok[128];
    int mtile = blockIdx.x, ntile = blockIdx.y, rd = blockIdx.z;
    int branch = rd >> 1, dir = rd & 1;
    const float* Wih = (dir ? Wih_b : Wih_f) + (size_t)branch * GDIM * EDIM;
    const float* bi  = (dir ? bih_b : bih_f) + branch * GDIM;
    const float* bh  = (dir ? bhh_b : bhh_f) + branch * GDIM;
    int tid = threadIdx.x;
    int m0 = mtile * 128, n0 = ntile * 64;
    if (tid < 128) {
        int m = m0 + tid;
        int s = m >> 6, b = m & 63;
        tok[tid] = x[b * SEQ + s];
    }
    int lane = tid & 31, wid = tid >> 5;
    int g = lane >> 2, tg = lane & 3;
    int wm = wid & 3, wn = wid >> 2;
    int mbase = wm * 32, nbase = wn * 32;
    float C[2][4][4];
#pragma unroll
    for (int mt = 0; mt < 2; mt++)
#pragma unroll
        for (int nt = 0; nt < 4; nt++)
#pragma unroll
            for (int q = 0; q < 4; q++) C[mt][nt][q] = 0.0f;
    __syncthreads();

    for (int k0 = 0; k0 < 304; k0 += 16) {
#pragma unroll
        for (int i = 0; i < 4; i++) {
            int task = tid + i * 256;
            int m = task >> 3, kp = task & 7;
            int k = k0 + 2 * kp;
            float2 v = (k < EDIM) ? *(const float2*)(emb + (size_t)tok[m] * EDIM + k)
                                  : make_float2(0.0f, 0.0f);
            *(ull*)&As_s[m * 20 + 2 * kp] = split2(v);
        }
#pragma unroll
        for (int i = 0; i < 2; i++) {
            int task = tid + i * 256;
            int n = task >> 3, kp = task & 7;
            int k = k0 + 2 * kp;
            float2 v = (k < EDIM) ? *(const float2*)(Wih + (size_t)(n0 + n) * EDIM + k)
                                  : make_float2(0.0f, 0.0f);
            *(ull*)&Bs_s[n * 20 + 2 * kp] = split2(v);
        }
        __syncthreads();

        u32 Ahi[2][4], Alo[2][4], Bhi[4][2], Blo[4][2];
#pragma unroll
        for (int mt = 0; mt < 2; mt++) {
            int r0 = mbase + mt * 16 + g;
            ull v0 = *(const ull*)&As_s[r0 * 20 + 2 * tg];
            ull v1 = *(const ull*)&As_s[(r0 + 8) * 20 + 2 * tg];
            ull v2 = *(const ull*)&As_s[r0 * 20 + 2 * (tg + 4)];
            ull v3 = *(const ull*)&As_s[(r0 + 8) * 20 + 2 * (tg + 4)];
            Ahi[mt][0] = (u32)v0; Alo[mt][0] = (u32)(v0 >> 32);
            Ahi[mt][1] = (u32)v1; Alo[mt][1] = (u32)(v1 >> 32);
            Ahi[mt][2] = (u32)v2; Alo[mt][2] = (u32)(v2 >> 32);
            Ahi[mt][3] = (u32)v3; Alo[mt][3] = (u32)(v3 >> 32);
        }
#pragma unroll
        for (int nt = 0; nt < 4; nt++) {
            int n = nbase + nt * 8 + g;
            ull v0 = *(const ull*)&Bs_s[n * 20 + 2 * tg];
            ull v1 = *(const ull*)&Bs_s[n * 20 + 2 * (tg + 4)];
            Bhi[nt][0] = (u32)v0; Blo[nt][0] = (u32)(v0 >> 32);
            Bhi[nt][1] = (u32)v1; Blo[nt][1] = (u32)(v1 >> 32);
        }
#pragma unroll
        for (int mt = 0; mt < 2; mt++)
#pragma unroll
            for (int nt = 0; nt < 4; nt++) {
                MMA_BF16(C[mt][nt], Ahi[mt], Bhi[nt]);
                MMA_BF16(C[mt][nt], Ahi[mt], Blo[nt]);
                MMA_BF16(C[mt][nt], Alo[mt], Bhi[nt]);
            }
        __syncthreads();
    }
#pragma unroll
    for (int mt = 0; mt < 2; mt++) {
#pragma unroll
        for (int rr = 0; rr < 2; rr++) {
            int m = m0 + mbase + mt * 16 + g + rr * 8;
            int s = m >> 6, b = m & 63;
            float* Pp = g_P + (((size_t)rd * SEQ + s) * BATCH + b) * GDIM + n0 + nbase;
#pragma unroll
            for (int nt = 0; nt < 4; nt++) {
                int nl = nt * 8 + 2 * tg;
                int nfull = n0 + nbase + nl;
                float2 o;
                o.x = C[mt][nt][rr * 2 + 0] + bi[nfull]     + bh[nfull];
                o.y = C[mt][nt][rr * 2 + 1] + bi[nfull + 1] + bh[nfull + 1];
                *(float2*)(Pp + nl) = o;
            }
        }
    }
}

// ---------------- phase 2: persistent recurrent scan  [bf16-split HMMA] -----------
// 80 blocks = 10 recs x 8 j-slices of 32. 8 warps: wm = wid&3 (m16 of batch 64),
// wn = wid>>2 (n64 of 128). Whh rows permuted: n' = wn*64 + 16*gate + jl16 so each
// thread's C fragment holds all 4 gates of its (b, j) units.
#define A_CHUNK 1032            // words/chunk: 64 rows * 16 + 8 pad
#define B_CHUNK 2056            // words/chunk: 128 rows * 16 + 8 pad
#define SCAN_SMEM ((16 * A_CHUNK + 16 * B_CHUNK) * 4)   // 197,632 B

__global__ void __launch_bounds__(256, 1)
k_scan(const float* __restrict__ Whh_f, const float* __restrict__ Whh_b) {
    extern __shared__ __align__(16) u32 smw[];
    u32* Bw = smw;                     // Whh split, resident
    u32* Aw = smw + 16 * B_CHUNK;      // h split, restaged per step

    int rd = blockIdx.x >> 3;
    int blk = blockIdx.x & 7;
    int j0 = blk * 32;
    int branch = rd >> 1, dir = rd & 1;
    const float* W = (dir ? Whh_b : Whh_f) + (size_t)branch * GDIM * HDIM;
    int tid = threadIdx.x;
    int lane = tid & 31, wid = tid >> 5;
    int g = lane >> 2, tg = lane & 3;
    int wm = wid & 3, wn = wid >> 2;
    int mbase = wm * 16, nbase = wn * 64;
    int xg = g << 1;                   // xor swizzle key (rows ≡ g mod 8)

    // ---- stage Whh slice (permuted rows, bf16 split), one time ----
    for (int p = tid; p < 128 * 128; p += 256) {
        int r = p >> 7;                 // n' 0..127
        int kpair = p & 127;
        int wnn = r >> 6, w = r & 63;
        int gate = w >> 4, jl = wnn * 16 + (w & 15);
        float2 v = *(const float2*)&W[(size_t)(gate * HDIM + j0 + jl) * HDIM + 2 * kpair];
        int idx = (kpair >> 3) * B_CHUNK + r * 16 + ((2 * (kpair & 7)) ^ ((r & 7) << 1));
        *(ull*)&Bw[idx] = split2(v);
    }
    float c[2][4];                      // [rr][jh*2+q]
#pragma unroll
    for (int a = 0; a < 2; a++)
#pragma unroll
        for (int b = 0; b < 4; b++) c[a][b] = 0.0f;
    __syncthreads();

    for (int t = 0; t < SEQ; ++t) {
        int sidx = dir ? (SEQ - 1 - t) : t;
        // prefetch P preacts for this thread's 32 output units
        const float* Pb = g_P + ((size_t)rd * SEQ + sidx) * BATCH * GDIM;
        float2 Pr[2][2][4];             // [rr][jh][gate]
#pragma unroll
        for (int rr = 0; rr < 2; rr++) {
            int b = mbase + g + 8 * rr;
#pragma unroll
            for (int jh = 0; jh < 2; jh++) {
                int j = j0 + wn * 16 + jh * 8 + 2 * tg;
#pragma unroll
                for (int gate = 0; gate < 4; gate++)
                    Pr[rr][jh][gate] = *(const float2*)&Pb[(size_t)b * GDIM + gate * HDIM + j];
            }
        }

        // stage h (f32 -> bf16 split) into Aw
        int par = t & 1;
        const float* Hin = &g_H[par][rd][0][0];
#pragma unroll
        for (int i = 0; i < 32; i++) {
            int p = tid + i * 256;
            int b = p >> 7, kpair = p & 127;
            float2 v = *(const float2*)&Hin[b * HDIM + 2 * kpair];
            int idx = (kpair >> 3) * A_CHUNK + b * 16 + ((2 * (kpair & 7)) ^ ((b & 7) << 1));
            *(ull*)&Aw[idx] = split2(v);
        }
        __syncthreads();

        float C[8][4];
#pragma unroll
        for (int nt = 0; nt < 8; nt++)
#pragma unroll
            for (int q = 0; q < 4; q++) C[nt][q] = 0.0f;

#pragma unroll 4
        for (int chunk = 0; chunk < 16; chunk++) {
            const u32* Ac = Aw + chunk * A_CHUNK;
            const u32* Bc = Bw + chunk * B_CHUNK;
            u32 Ahi[4], Alo[4];
            {
                int r0 = mbase + g;
                ull v0 = *(const ull*)&Ac[r0 * 16 + ((2 * tg) ^ xg)];
                ull v1 = *(const ull*)&Ac[(r0 + 8) * 16 + ((2 * tg) ^ xg)];
                ull v2 = *(const ull*)&Ac[r0 * 16 + ((2 * (tg + 4)) ^ xg)];
                ull v3 = *(const ull*)&Ac[(r0 + 8) * 16 + ((2 * (tg + 4)) ^ xg)];
                Ahi[0] = (u32)v0; Alo[0] = (u32)(v0 >> 32);
                Ahi[1] = (u32)v1; Alo[1] = (u32)(v1 >> 32);
                Ahi[2] = (u32)v2; Alo[2] = (u32)(v2 >> 32);
                Ahi[3] = (u32)v3; Alo[3] = (u32)(v3 >> 32);
            }
#pragma unroll
            for (int nt = 0; nt < 8; nt++) {
                int n = nbase + nt * 8 + g;
                ull v0 = *(const ull*)&Bc[n * 16 + ((2 * tg) ^ xg)];
                ull v1 = *(const ull*)&Bc[n * 16 + ((2 * (tg + 4)) ^ xg)];
                u32 Bhi[2], Blo[2];
                Bhi[0] = (u32)v0; Blo[0] = (u32)(v0 >> 32);
                Bhi[1] = (u32)v1; Blo[1] = (u32)(v1 >> 32);
                MMA_BF16(C[nt], Ahi, Bhi);
                MMA_BF16(C[nt], Ahi, Blo);
                MMA_BF16(C[nt], Alo, Bhi);
            }
        }

        // epilogue: gates + cell update, all register-local
        float* Hout = &g_H[par ^ 1][rd][0][0];
        float* HSo = g_HS + ((size_t)rd * SEQ + sidx) * BATCH * HDIM;
#pragma unroll
        for (int rr = 0; rr < 2; rr++) {
            int b = mbase + g + 8 * rr;
#pragma unroll
            for (int jh = 0; jh < 2; jh++) {
                int j = j0 + wn * 16 + jh * 8 + 2 * tg;
                float2 hv;
#pragma unroll
                for (int q = 0; q < 1; q++) {}  // (placeholder keeps unroll structure)
                {
                    float iv0 = C[0 + jh][rr * 2 + 0] + Pr[rr][jh][0].x;
                    float fv0 = C[2 + jh][rr * 2 + 0] + Pr[rr][jh][1].x;
                    float gv0 = C[4 + jh][rr * 2 + 0] + Pr[rr][jh][2].x;
                    float ov0 = C[6 + jh][rr * 2 + 0] + Pr[rr][jh][3].x;
                    float iv1 = C[0 + jh][rr * 2 + 1] + Pr[rr][jh][0].y;
                    float fv1 = C[2 + jh][rr * 2 + 1] + Pr[rr][jh][1].y;
                    float gv1 = C[4 + jh][rr * 2 + 1] + Pr[rr][jh][2].y;
                    float ov1 = C[6 + jh][rr * 2 + 1] + Pr[rr][jh][3].y;
                    float cn0 = fsigm(fv0) * c[rr][jh * 2 + 0] + fsigm(iv0) * ftanh(gv0);
                    float cn1 = fsigm(fv1) * c[rr][jh * 2 + 1] + fsigm(iv1) * ftanh(gv1);
                    c[rr][jh * 2 + 0] = cn0;
                    c[rr][jh * 2 + 1] = cn1;
                    hv.x = fsigm(ov0) * ftanh(cn0);
                    hv.y = fsigm(ov1) * ftanh(cn1);
                }
                *(float2*)&Hout[b * HDIM + j] = hv;
                *(float2*)&HSo[(size_t)b * HDIM + j] = hv;
            }
        }
        // inter-block step barrier (per recurrence)
        __syncthreads();
        if (tid == 0) {
            __threadfence();
            atomicAdd(&g_cnt[rd], 1u);
            unsigned target = 8u * (unsigned)(t + 1);
            while (atomicAdd(&g_cnt[rd], 0u) < target) __nanosleep(64);
            __threadfence();
        }
        __syncthreads();
    }
}

// ---------------- phase 3a: attention logits  [bf16-split HMMA, fused tanh+watt] --
__global__ void k_logits(const float* __restrict__ Wa, const float* __restrict__ ba,
                         const float* __restrict__ watt) {
    __shared__ __align__(8) u32 As_s[128 * 20];
    __shared__ __align__(8) u32 Bs_s[64 * 20];
    int mtile = blockIdx.x, ntile = blockIdx.y, br = blockIdx.z;
    const float* W = Wa + (size_t)br * ADIM * ADIM;
    int tid = threadIdx.x;
    int m0 = mtile * 128, n0 = ntile * 64;
    int lane = tid & 31, wid = tid >> 5;
    int g = lane >> 2, tg = lane & 3;
    int wm = wid & 3, wn = wid >> 2;
    int mbase = wm * 32, nbase = wn * 32;
    float C[2][4][4];
#pragma unroll
    for (int mt = 0; mt < 2; mt++)
#pragma unroll
        for (int nt = 0; nt < 4; nt++)
#pragma unroll
            for (int q = 0; q < 4; q++) C[mt][nt][q] = 0.0f;

    for (int k0 = 0; k0 < ADIM; k0 += 16) {
#pragma unroll
        for (int i = 0; i < 4; i++) {
            int task = tid + i * 256;
            int m = task >> 3, kp = task & 7;
            int k = k0 + 2 * kp;
            int mm = m0 + m;
            int s = mm >> 6, b = mm & 63;
            int rdh = 2 * br + (k >> 8);
            int dd = k & 255;
            float2 v = *(const float2*)(g_HS + (((size_t)rdh * SEQ + s) * BATCH + b) * HDIM + dd);
            *(ull*)&As_s[m * 20 + 2 * kp] = split2(v);
        }
#pragma unroll
        for (int i = 0; i < 2; i++) {
            int task = tid + i * 256;
            int n = task >> 3, kp = task & 7;
            int k = k0 + 2 * kp;
            float2 v = *(const float2*)(W + (size_t)(n0 + n) * ADIM + k);
            *(ull*)&Bs_s[n * 20 + 2 * kp] = split2(v);
        }
        __syncthreads();

        u32 Ahi[2][4], Alo[2][4], Bhi[4][2], Blo[4][2];
#pragma unroll
        for (int mt = 0; mt < 2; mt++) {
            int r0 = mbase + mt * 16 + g;
            ull v0 = *(const ull*)&As_s[r0 * 20 + 2 * tg];
            ull v1 = *(const ull*)&As_s[(r0 + 8) * 20 + 2 * tg];
            ull v2 = *(const ull*)&As_s[r0 * 20 + 2 * (tg + 4)];
            ull v3 = *(const ull*)&As_s[(r0 + 8) * 20 + 2 * (tg + 4)];
            Ahi[mt][0] = (u32)v0; Alo[mt][0] = (u32)(v0 >> 32);
            Ahi[mt][1] = (u32)v1; Alo[mt][1] = (u32)(v1 >> 32);
            Ahi[mt][2] = (u32)v2; Alo[mt][2] = (u32)(v2 >> 32);
            Ahi[mt][3] = (u32)v3; Alo[mt][3] = (u32)(v3 >> 32);
        }
#pragma unroll
        for (int nt = 0; nt < 4; nt++) {
            int n = nbase + nt * 8 + g;
            ull v0 = *(const ull*)&Bs_s[n * 20 + 2 * tg];
            ull v1 = *(const ull*)&Bs_s[n * 20 + 2 * (tg + 4)];
            Bhi[nt][0] = (u32)v0; Blo[nt][0] = (u32)(v0 >> 32);
            Bhi[nt][1] = (u32)v1; Blo[nt][1] = (u32)(v1 >> 32);
        }
#pragma unroll
        for (int mt = 0; mt < 2; mt++)
#pragma unroll
            for (int nt = 0; nt < 4; nt++) {
                MMA_BF16(C[mt][nt], Ahi[mt], Bhi[nt]);
                MMA_BF16(C[mt][nt], Ahi[mt], Blo[nt]);
                MMA_BF16(C[mt][nt], Alo[mt], Bhi[nt]);
            }
        __syncthreads();
    }
#pragma unroll
    for (int mt = 0; mt < 2; mt++) {
        float p0 = 0.0f, p1 = 0.0f;
#pragma unroll
        for (int nt = 0; nt < 4; nt++) {
            int nfull = n0 + nbase + nt * 8 + 2 * tg;
            float ba0 = ba[br * ADIM + nfull],     wa0 = watt[br * ADIM + nfull];
            float ba1 = ba[br * ADIM + nfull + 1], wa1 = watt[br * ADIM + nfull + 1];
            p0 += ftanh(C[mt][nt][0] + ba0) * wa0 + ftanh(C[mt][nt][1] + ba1) * wa1;
            p1 += ftanh(C[mt][nt][2] + ba0) * wa0 + ftanh(C[mt][nt][3] + ba1) * wa1;
        }
        p0 += __shfl_xor_sync(0xffffffffu, p0, 1);
        p0 += __shfl_xor_sync(0xffffffffu, p0, 2);
        p1 += __shfl_xor_sync(0xffffffffu, p1, 1);
        p1 += __shfl_xor_sync(0xffffffffu, p1, 2);
        if (tg == 0) {
            int m = m0 + mbase + mt * 16 + g;
            int s = m >> 6, b = m & 63;
            atomicAdd(&g_logit[br][b][s], p0);
            int m2 = m + 8;
            int s2 = m2 >> 6, b2 = m2 & 63;
            atomicAdd(&g_logit[br][b2][s2], p1);
        }
    }
}

// ---------------- phase 3b: softmax over S -------------------------------------
__global__ void k_softmax() {
    int br = blockIdx.x >> 6, b = blockIdx.x & 63;
    __shared__ float red[256];
    const float* L = &g_logit[br][b][0];
    int tid = threadIdx.x;
    float m1 = fmaxf(L[tid], L[tid + 256]);
    red[tid] = m1; __syncthreads();
    for (int o = 128; o > 0; o >>= 1) { if (tid < o) red[tid] = fmaxf(red[tid], red[tid + o]); __syncthreads(); }
    float mx = red[0]; __syncthreads();
    float e0 = __expf(L[tid] - mx), e1 = __expf(L[tid + 256] - mx);
    red[tid] = e0 + e1; __syncthreads();
    for (int o = 128; o > 0; o >>= 1) { if (tid < o) red[tid] += red[tid + o]; __syncthreads(); }
    float inv = 1.0f / red[0];
    g_attw[br][b][tid] = e0 * inv;
    g_attw[br][b][tid + 256] = e1 * inv;
}

// ---------------- phase 3c: attention-weighted sum ------------------------------
__global__ void k_attsum() {
    int b = blockIdx.x, br = blockIdx.y;
    int d = threadIdx.x;   // 512 threads
    __shared__ float aw[512];
    aw[d] = g_attw[br][b][d];
    __syncthreads();
    int rdh = (d < HDIM) ? (2 * br) : (2 * br + 1);
    int dd = d & 255;
    const float* base = g_HS + (size_t)rdh * SEQ * BATCH * HDIM + (size_t)b * HDIM + dd;
    float a0 = 0.0f, a1 = 0.0f;
    for (int s = 0; s < SEQ; s += 2) {
        a0 = fmaf(aw[s],     base[(size_t)s * BATCH * HDIM], a0);
        a1 = fmaf(aw[s + 1], base[(size_t)(s + 1) * BATCH * HDIM], a1);
    }
    g_ATT[br][b][d] = a0 + a1;
}

// ---------------- phase 4: routed final FC --------------------------------------
__global__ void k_final(const int* __restrict__ z, const float* __restrict__ Wfc,
                        const float* __restrict__ bfc, float* __restrict__ out) {
    int b = blockIdx.x;
    int tid = threadIdx.x;   // 256
    int zb = z[b];
    __shared__ float red0[256], red1[256];
    float a0 = 0.0f, a1 = 0.0f;
    for (int k = tid; k < 1024; k += 256) {
        float v = (k < 512) ? g_ATT[zb + 1][b][k] : g_ATT[0][b][k - 512];
        a0 = fmaf(v, Wfc[k], a0);
        a1 = fmaf(v, Wfc[1024 + k], a1);
    }
    red0[tid] = a0; red1[tid] = a1; __syncthreads();
    for (int o = 128; o > 0; o >>= 1) {
        if (tid < o) { red0[tid] += red0[tid + o]; red1[tid] += red1[tid + o]; }
        __syncthreads();
    }
    if (tid == 0) {
        out[b * 2 + 0] = red0[0] + bfc[0];
        out[b * 2 + 1] = red1[0] + bfc[1];
    }
}

// ---------------- copy general + specifics into d_out ---------------------------
__global__ void k_copyout(float* __restrict__ out) {
    int idx = blockIdx.x * blockDim.x + threadIdx.x;
    const float* A = &g_ATT[0][0][0];
    if (idx < NBR * BATCH * ADIM) out[128 + idx] = A[idx];
}

// ---------------- launcher -------------------------------------------------------
extern "C" void kernel_launch(void* const* d_in, const int* in_sizes, int n_in,
                              void* d_out, int out_size) {
    const int*   x     = (const int*)  d_in[0];
    const int*   z     = (const int*)  d_in[1];
    const float* emb   = (const float*)d_in[2];
    const float* Wih_f = (const float*)d_in[3];
    const float* Whh_f = (const float*)d_in[4];
    const float* bih_f = (const float*)d_in[5];
    const float* bhh_f = (const float*)d_in[6];
    const float* Wih_b = (const float*)d_in[7];
    const float* Whh_b = (const float*)d_in[8];
    const float* bih_b = (const float*)d_in[9];
    const float* bhh_b = (const float*)d_in[10];
    const float* Wa    = (const float*)d_in[11];
    const float* ba    = (const float*)d_in[12];
    const float* watt  = (const float*)d_in[13];
    const float* Wfc   = (const float*)d_in[14];
    const float* bfc   = (const float*)d_in[15];
    float* out = (float*)d_out;

    cudaFuncSetAttribute(k_scan, cudaFuncAttributeMaxDynamicSharedMemorySize, SCAN_SMEM);

    k_init<<<1280, 256>>>();
    k_inputproj<<<dim3(256, 16, 10), 256>>>(x, emb, Wih_f, Wih_b, bih_f, bhh_f, bih_b, bhh_b);
    k_scan<<<80, 256, SCAN_SMEM>>>(Whh_f, Whh_b);
    k_logits<<<dim3(256, 8, 5), 256>>>(Wa, ba, watt);
    k_softmax<<<320, 256>>>();
    k_attsum<<<dim3(64, 5), 512>>>();
    k_final<<<64, 256>>>(z, Wfc, bfc, out);
    k_copyout<<<640, 256>>>(out);
}

// round 7
// speedup vs baseline: 2.6823x; 1.0030x over previous
#include <cuda_runtime.h>
#include <cuda_bf16.h>

#define HDIM   256
#define GDIM   1024      // 4*H
#define BATCH  64
#define SEQ    512
#define NRD    10        // 5 branches * 2 directions
#define NBR    5
#define EDIM   300
#define ADIM   512       // 2*H

typedef unsigned long long ull;
typedef unsigned int u32;

// ---------------- scratch (device globals; no allocation allowed) ----------------
__device__ float g_P [335544320];   // [NRD][SEQ][BATCH][GDIM]
__device__ float g_HS[ 83886080];   // [NRD][SEQ][BATCH][HDIM]
__device__ float g_H [2][NRD][BATCH][HDIM];
__device__ float g_ATT[NBR][BATCH][ADIM];
__device__ float g_logit[NBR][BATCH][SEQ];
__device__ float g_attw [NBR][BATCH][SEQ];
__device__ unsigned g_cnt[NRD];

__device__ __forceinline__ float fsigm(float x) { return 1.0f / (1.0f + __expf(-x)); }
__device__ __forceinline__ float ftanh(float x) { return 1.0f - 2.0f / (__expf(2.0f * x) + 1.0f); }

// bf16 2-term split of a float pair -> (hi word | lo word << 32)
__device__ __forceinline__ ull split2(float2 v) {
    __nv_bfloat162 h = __floats2bfloat162_rn(v.x, v.y);
    float r0 = v.x - __bfloat162float(h.x);
    float r1 = v.y - __bfloat162float(h.y);
    __nv_bfloat162 l = __floats2bfloat162_rn(r0, r1);
    u32 hw = *(u32*)&h;
    u32 lw = *(u32*)&l;
    return (ull)hw | ((ull)lw << 32);
}

#define MMA_BF16(c, a, b) \
    asm volatile("mma.sync.aligned.m16n8k16.row.col.f32.bf16.bf16.f32 " \
                 "{%0,%1,%2,%3}, {%4,%5,%6,%7}, {%8,%9}, {%0,%1,%2,%3};" \
                 : "+f"((c)[0]), "+f"((c)[1]), "+f"((c)[2]), "+f"((c)[3]) \
                 : "r"((a)[0]), "r"((a)[1]), "r"((a)[2]), "r"((a)[3]), \
                   "r"((b)[0]), "r"((b)[1]))

// ---------------- init -----------------------------------------------------------
__global__ void k_init() {
    int idx = blockIdx.x * blockDim.x + threadIdx.x;
    if (idx < 2 * NRD * BATCH * HDIM) ((float*)g_H)[idx] = 0.0f;
    if (idx < NBR * BATCH * SEQ)      ((float*)g_logit)[idx] = 0.0f;
    if (idx < NRD)                    g_cnt[idx] = 0u;
}

// ---------------- phase 1: P = emb[x] @ Wih.T + (bih+bhh)  [bf16-split HMMA] ------
__global__ void k_inputproj(const int* __restrict__ x, const float* __restrict__ emb,
                            const float* __restrict__ Wih_f, const float* __restrict__ Wih_b,
                            const float* __restrict__ bih_f, const float* __restrict__ bhh_f,
                            const float* __restrict__ bih_b, const float* __restrict__ bhh_b) {
    __shared__ __align__(8) u32 As_s[128 * 20];   // [m][kp*2 + {hi,lo}]
    __shared__ __align__(8) u32 Bs_s[64 * 20];
    __shared__ int tok[128];
    int mtile = blockIdx.x, ntile = blockIdx.y, rd = blockIdx.z;
    int branch = rd >> 1, dir = rd & 1;
    const float* Wih = (dir ? Wih_b : Wih_f) + (size_t)branch * GDIM * EDIM;
    const float* bi  = (dir ? bih_b : bih_f) + branch * GDIM;
    const float* bh  = (dir ? bhh_b : bhh_f) + branch * GDIM;
    int tid = threadIdx.x;
    int m0 = mtile * 128, n0 = ntile * 64;
    if (tid < 128) {
        int m = m0 + tid;
        int s = m >> 6, b = m & 63;
        tok[tid] = x[b * SEQ + s];
    }
    int lane = tid & 31, wid = tid >> 5;
    int g = lane >> 2, tg = lane & 3;
    int wm = wid & 3, wn = wid >> 2;
    int mbase = wm * 32, nbase = wn * 32;
    float C[2][4][4];
#pragma unroll
    for (int mt = 0; mt < 2; mt++)
#pragma unroll
        for (int nt = 0; nt < 4; nt++)
#pragma unroll
            for (int q = 0; q < 4; q++) C[mt][nt][q] = 0.0f;
    __syncthreads();

    for (int k0 = 0; k0 < 304; k0 += 16) {
#pragma unroll
        for (int i = 0; i < 4; i++) {
            int task = tid + i * 256;
            int m = task >> 3, kp = task & 7;
            int k = k0 + 2 * kp;
            float2 v = (k < EDIM) ? *(const float2*)(emb + (size_t)tok[m] * EDIM + k)
                                  : make_float2(0.0f, 0.0f);
            *(ull*)&As_s[m * 20 + 2 * kp] = split2(v);
        }
#pragma unroll
        for (int i = 0; i < 2; i++) {
            int task = tid + i * 256;
            int n = task >> 3, kp = task & 7;
            int k = k0 + 2 * kp;
            float2 v = (k < EDIM) ? *(const float2*)(Wih + (size_t)(n0 + n) * EDIM + k)
                                  : make_float2(0.0f, 0.0f);
            *(ull*)&Bs_s[n * 20 + 2 * kp] = split2(v);
        }
        __syncthreads();

        u32 Ahi[2][4], Alo[2][4], Bhi[4][2], Blo[4][2];
#pragma unroll
        for (int mt = 0; mt < 2; mt++) {
            int r0 = mbase + mt * 16 + g;
            ull v0 = *(const ull*)&As_s[r0 * 20 + 2 * tg];
            ull v1 = *(const ull*)&As_s[(r0 + 8) * 20 + 2 * tg];
            ull v2 = *(const ull*)&As_s[r0 * 20 + 2 * (tg + 4)];
            ull v3 = *(const ull*)&As_s[(r0 + 8) * 20 + 2 * (tg + 4)];
            Ahi[mt][0] = (u32)v0; Alo[mt][0] = (u32)(v0 >> 32);
            Ahi[mt][1] = (u32)v1; Alo[mt][1] = (u32)(v1 >> 32);
            Ahi[mt][2] = (u32)v2; Alo[mt][2] = (u32)(v2 >> 32);
            Ahi[mt][3] = (u32)v3; Alo[mt][3] = (u32)(v3 >> 32);
        }
#pragma unroll
        for (int nt = 0; nt < 4; nt++) {
            int n = nbase + nt * 8 + g;
            ull v0 = *(const ull*)&Bs_s[n * 20 + 2 * tg];
            ull v1 = *(const ull*)&Bs_s[n * 20 + 2 * (tg + 4)];
            Bhi[nt][0] = (u32)v0; Blo[nt][0] = (u32)(v0 >> 32);
            Bhi[nt][1] = (u32)v1; Blo[nt][1] = (u32)(v1 >> 32);
        }
#pragma unroll
        for (int mt = 0; mt < 2; mt++)
#pragma unroll
            for (int nt = 0; nt < 4; nt++) {
                MMA_BF16(C[mt][nt], Ahi[mt], Bhi[nt]);
                MMA_BF16(C[mt][nt], Ahi[mt], Blo[nt]);
                MMA_BF16(C[mt][nt], Alo[mt], Bhi[nt]);
            }
        __syncthreads();
    }
#pragma unroll
    for (int mt = 0; mt < 2; mt++) {
#pragma unroll
        for (int rr = 0; rr < 2; rr++) {
            int m = m0 + mbase + mt * 16 + g + rr * 8;
            int s = m >> 6, b = m & 63;
            float* Pp = g_P + (((size_t)rd * SEQ + s) * BATCH + b) * GDIM + n0 + nbase;
#pragma unroll
            for (int nt = 0; nt < 4; nt++) {
                int nl = nt * 8 + 2 * tg;
                int nfull = n0 + nbase + nl;
                float2 o;
                o.x = C[mt][nt][rr * 2 + 0] + bi[nfull]     + bh[nfull];
                o.y = C[mt][nt][rr * 2 + 1] + bi[nfull + 1] + bh[nfull + 1];
                *(float2*)(Pp + nl) = o;
            }
        }
    }
}

// ---------------- phase 2: persistent recurrent scan  [bf16-split HMMA] -----------
// 80 blocks = 10 recs x 8 j-slices of 32. 8 warps: wm = wid&3 (m16 of batch 64),
// wn = wid>>2 (n64 of 128). Whh rows permuted: n' = wn*64 + 16*gate + jl16 so each
// thread's C fragment holds all 4 gates of its (b, j) units.
#define A_CHUNK 1032            // words/chunk: 64 rows * 16 + 8 pad
#define B_CHUNK 2056            // words/chunk: 128 rows * 16 + 8 pad
#define SCAN_SMEM ((16 * A_CHUNK + 16 * B_CHUNK) * 4)   // 197,632 B

__global__ void __launch_bounds__(256, 1)
k_scan(const float* __restrict__ Whh_f, const float* __restrict__ Whh_b) {
    extern __shared__ __align__(16) u32 smw[];
    u32* Bw = smw;                     // Whh split, resident
    u32* Aw = smw + 16 * B_CHUNK;      // h split, restaged per step

    int rd = blockIdx.x >> 3;
    int blk = blockIdx.x & 7;
    int j0 = blk * 32;
    int branch = rd >> 1, dir = rd & 1;
    const float* W = (dir ? Whh_b : Whh_f) + (size_t)branch * GDIM * HDIM;
    int tid = threadIdx.x;
    int lane = tid & 31, wid = tid >> 5;
    int g = lane >> 2, tg = lane & 3;
    int wm = wid & 3, wn = wid >> 2;
    int mbase = wm * 16, nbase = wn * 64;
    int xg = g << 1;                   // xor swizzle key (rows ≡ g mod 8)

    // ---- stage Whh slice (permuted rows, bf16 split), one time ----
    for (int p = tid; p < 128 * 128; p += 256) {
        int r = p >> 7;                 // n' 0..127
        int kpair = p & 127;
        int wnn = r >> 6, w = r & 63;
        int gate = w >> 4, jl = wnn * 16 + (w & 15);
        float2 v = *(const float2*)&W[(size_t)(gate * HDIM + j0 + jl) * HDIM + 2 * kpair];
        int idx = (kpair >> 3) * B_CHUNK + r * 16 + ((2 * (kpair & 7)) ^ ((r & 7) << 1));
        *(ull*)&Bw[idx] = split2(v);
    }
    float c[2][4];                      // [rr][jh*2+q]
#pragma unroll
    for (int a = 0; a < 2; a++)
#pragma unroll
        for (int b = 0; b < 4; b++) c[a][b] = 0.0f;
    __syncthreads();

    for (int t = 0; t < SEQ; ++t) {
        int sidx = dir ? (SEQ - 1 - t) : t;
        // prefetch P preacts for this thread's 32 output units
        const float* Pb = g_P + ((size_t)rd * SEQ + sidx) * BATCH * GDIM;
        float2 Pr[2][2][4];             // [rr][jh][gate]
#pragma unroll
        for (int rr = 0; rr < 2; rr++) {
            int b = mbase + g + 8 * rr;
#pragma unroll
            for (int jh = 0; jh < 2; jh++) {
                int j = j0 + wn * 16 + jh * 8 + 2 * tg;
#pragma unroll
                for (int gate = 0; gate < 4; gate++)
                    Pr[rr][jh][gate] = *(const float2*)&Pb[(size_t)b * GDIM + gate * HDIM + j];
            }
        }

        // stage h (f32 -> bf16 split) into Aw
        int par = t & 1;
        const float* Hin = &g_H[par][rd][0][0];
#pragma unroll
        for (int i = 0; i < 32; i++) {
            int p = tid + i * 256;
            int b = p >> 7, kpair = p & 127;
            float2 v = *(const float2*)&Hin[b * HDIM + 2 * kpair];
            int idx = (kpair >> 3) * A_CHUNK + b * 16 + ((2 * (kpair & 7)) ^ ((b & 7) << 1));
            *(ull*)&Aw[idx] = split2(v);
        }
        __syncthreads();

        float C[8][4];
#pragma unroll
        for (int nt = 0; nt < 8; nt++)
#pragma unroll
            for (int q = 0; q < 4; q++) C[nt][q] = 0.0f;

#pragma unroll 4
        for (int chunk = 0; chunk < 16; chunk++) {
            const u32* Ac = Aw + chunk * A_CHUNK;
            const u32* Bc = Bw + chunk * B_CHUNK;
            u32 Ahi[4], Alo[4];
            {
                int r0 = mbase + g;
                ull v0 = *(const ull*)&Ac[r0 * 16 + ((2 * tg) ^ xg)];
                ull v1 = *(const ull*)&Ac[(r0 + 8) * 16 + ((2 * tg) ^ xg)];
                ull v2 = *(const ull*)&Ac[r0 * 16 + ((2 * (tg + 4)) ^ xg)];
                ull v3 = *(const ull*)&Ac[(r0 + 8) * 16 + ((2 * (tg + 4)) ^ xg)];
                Ahi[0] = (u32)v0; Alo[0] = (u32)(v0 >> 32);
                Ahi[1] = (u32)v1; Alo[1] = (u32)(v1 >> 32);
                Ahi[2] = (u32)v2; Alo[2] = (u32)(v2 >> 32);
                Ahi[3] = (u32)v3; Alo[3] = (u32)(v3 >> 32);
            }
#pragma unroll
            for (int nt = 0; nt < 8; nt++) {
                int n = nbase + nt * 8 + g;
                ull v0 = *(const ull*)&Bc[n * 16 + ((2 * tg) ^ xg)];
                ull v1 = *(const ull*)&Bc[n * 16 + ((2 * (tg + 4)) ^ xg)];
                u32 Bhi[2], Blo[2];
                Bhi[0] = (u32)v0; Blo[0] = (u32)(v0 >> 32);
                Bhi[1] = (u32)v1; Blo[1] = (u32)(v1 >> 32);
                MMA_BF16(C[nt], Ahi, Bhi);
                MMA_BF16(C[nt], Ahi, Blo);
                MMA_BF16(C[nt], Alo, Bhi);
            }
        }

        // epilogue: gates + cell update, all register-local
        float* Hout = &g_H[par ^ 1][rd][0][0];
        float* HSo = g_HS + ((size_t)rd * SEQ + sidx) * BATCH * HDIM;
#pragma unroll
        for (int rr = 0; rr < 2; rr++) {
            int b = mbase + g + 8 * rr;
#pragma unroll
            for (int jh = 0; jh < 2; jh++) {
                int j = j0 + wn * 16 + jh * 8 + 2 * tg;
                float2 hv;
#pragma unroll
                for (int q = 0; q < 1; q++) {}  // (placeholder keeps unroll structure)
                {
                    float iv0 = C[0 + jh][rr * 2 + 0] + Pr[rr][jh][0].x;
                    float fv0 = C[2 + jh][rr * 2 + 0] + Pr[rr][jh][1].x;
                    float gv0 = C[4 + jh][rr * 2 + 0] + Pr[rr][jh][2].x;
                    float ov0 = C[6 + jh][rr * 2 + 0] + Pr[rr][jh][3].x;
                    float iv1 = C[0 + jh][rr * 2 + 1] + Pr[rr][jh][0].y;
                    float fv1 = C[2 + jh][rr * 2 + 1] + Pr[rr][jh][1].y;
                    float gv1 = C[4 + jh][rr * 2 + 1] + Pr[rr][jh][2].y;
                    float ov1 = C[6 + jh][rr * 2 + 1] + Pr[rr][jh][3].y;
                    float cn0 = fsigm(fv0) * c[rr][jh * 2 + 0] + fsigm(iv0) * ftanh(gv0);
                    float cn1 = fsigm(fv1) * c[rr][jh * 2 + 1] + fsigm(iv1) * ftanh(gv1);
                    c[rr][jh * 2 + 0] = cn0;
                    c[rr][jh * 2 + 1] = cn1;
                    hv.x = fsigm(ov0) * ftanh(cn0);
                    hv.y = fsigm(ov1) * ftanh(cn1);
                }
                *(float2*)&Hout[b * HDIM + j] = hv;
                *(float2*)&HSo[(size_t)b * HDIM + j] = hv;
            }
        }
        // inter-block step barrier (per recurrence)
        __syncthreads();
        if (tid == 0) {
            __threadfence();
            atomicAdd(&g_cnt[rd], 1u);
            unsigned target = 8u * (unsigned)(t + 1);
            while (atomicAdd(&g_cnt[rd], 0u) < target) __nanosleep(64);
            __threadfence();
        }
        __syncthreads();
    }
}

// ---------------- phase 3a: attention logits  [bf16-split HMMA, fused tanh+watt] --
__global__ void k_logits(const float* __restrict__ Wa, const float* __restrict__ ba,
                         const float* __restrict__ watt) {
    __shared__ __align__(8) u32 As_s[128 * 20];
    __shared__ __align__(8) u32 Bs_s[64 * 20];
    int mtile = blockIdx.x, ntile = blockIdx.y, br = blockIdx.z;
    const float* W = Wa + (size_t)br * ADIM * ADIM;
    int tid = threadIdx.x;
    int m0 = mtile * 128, n0 = ntile * 64;
    int lane = tid & 31, wid = tid >> 5;
    int g = lane >> 2, tg = lane & 3;
    int wm = wid & 3, wn = wid >> 2;
    int mbase = wm * 32, nbase = wn * 32;
    float C[2][4][4];
#pragma unroll
    for (int mt = 0; mt < 2; mt++)
#pragma unroll
        for (int nt = 0; nt < 4; nt++)
#pragma unroll
            for (int q = 0; q < 4; q++) C[mt][nt][q] = 0.0f;

    for (int k0 = 0; k0 < ADIM; k0 += 16) {
#pragma unroll
        for (int i = 0; i < 4; i++) {
            int task = tid + i * 256;
            int m = task >> 3, kp = task & 7;
            int k = k0 + 2 * kp;
            int mm = m0 + m;
            int s = mm >> 6, b = mm & 63;
            int rdh = 2 * br + (k >> 8);
            int dd = k & 255;
            float2 v = *(const float2*)(g_HS + (((size_t)rdh * SEQ + s) * BATCH + b) * HDIM + dd);
            *(ull*)&As_s[m * 20 + 2 * kp] = split2(v);
        }
#pragma unroll
        for (int i = 0; i < 2; i++) {
            int task = tid + i * 256;
            int n = task >> 3, kp = task & 7;
            int k = k0 + 2 * kp;
            float2 v = *(const float2*)(W + (size_t)(n0 + n) * ADIM + k);
            *(ull*)&Bs_s[n * 20 + 2 * kp] = split2(v);
        }
        __syncthreads();

        u32 Ahi[2][4], Alo[2][4], Bhi[4][2], Blo[4][2];
#pragma unroll
        for (int mt = 0; mt < 2; mt++) {
            int r0 = mbase + mt * 16 + g;
            ull v0 = *(const ull*)&As_s[r0 * 20 + 2 * tg];
            ull v1 = *(const ull*)&As_s[(r0 + 8) * 20 + 2 * tg];
            ull v2 = *(const ull*)&As_s[r0 * 20 + 2 * (tg + 4)];
            ull v3 = *(const ull*)&As_s[(r0 + 8) * 20 + 2 * (tg + 4)];
            Ahi[mt][0] = (u32)v0; Alo[mt][0] = (u32)(v0 >> 32);
            Ahi[mt][1] = (u32)v1; Alo[mt][1] = (u32)(v1 >> 32);
            Ahi[mt][2] = (u32)v2; Alo[mt][2] = (u32)(v2 >> 32);
            Ahi[mt][3] = (u32)v3; Alo[mt][3] = (u32)(v3 >> 32);
        }
#pragma unroll
        for (int nt = 0; nt < 4; nt++) {
            int n = nbase + nt * 8 + g;
            ull v0 = *(const ull*)&Bs_s[n * 20 + 2 * tg];
            ull v1 = *(const ull*)&Bs_s[n * 20 + 2 * (tg + 4)];
            Bhi[nt][0] = (u32)v0; Blo[nt][0] = (u32)(v0 >> 32);
            Bhi[nt][1] = (u32)v1; Blo[nt][1] = (u32)(v1 >> 32);
        }
#pragma unroll
        for (int mt = 0; mt < 2; mt++)
#pragma unroll
            for (int nt = 0; nt < 4; nt++) {
                MMA_BF16(C[mt][nt], Ahi[mt], Bhi[nt]);
                MMA_BF16(C[mt][nt], Ahi[mt], Blo[nt]);
                MMA_BF16(C[mt][nt], Alo[mt], Bhi[nt]);
            }
        __syncthreads();
    }
#pragma unroll
    for (int mt = 0; mt < 2; mt++) {
        float p0 = 0.0f, p1 = 0.0f;
#pragma unroll
        for (int nt = 0; nt < 4; nt++) {
            int nfull = n0 + nbase + nt * 8 + 2 * tg;
            float ba0 = ba[br * ADIM + nfull],     wa0 = watt[br * ADIM + nfull];
            float ba1 = ba[br * ADIM + nfull + 1], wa1 = watt[br * ADIM + nfull + 1];
            p0 += ftanh(C[mt][nt][0] + ba0) * wa0 + ftanh(C[mt][nt][1] + ba1) * wa1;
            p1 += ftanh(C[mt][nt][2] + ba0) * wa0 + ftanh(C[mt][nt][3] + ba1) * wa1;
        }
        p0 += __shfl_xor_sync(0xffffffffu, p0, 1);
        p0 += __shfl_xor_sync(0xffffffffu, p0, 2);
        p1 += __shfl_xor_sync(0xffffffffu, p1, 1);
        p1 += __shfl_xor_sync(0xffffffffu, p1, 2);
        if (tg == 0) {
            int m = m0 + mbase + mt * 16 + g;
            int s = m >> 6, b = m & 63;
            atomicAdd(&g_logit[br][b][s], p0);
            int m2 = m + 8;
            int s2 = m2 >> 6, b2 = m2 & 63;
            atomicAdd(&g_logit[br][b2][s2], p1);
        }
    }
}

// ---------------- phase 3b: softmax over S -------------------------------------
__global__ void k_softmax() {
    int br = blockIdx.x >> 6, b = blockIdx.x & 63;
    __shared__ float red[256];
    const float* L = &g_logit[br][b][0];
    int tid = threadIdx.x;
    float m1 = fmaxf(L[tid], L[tid + 256]);
    red[tid] = m1; __syncthreads();
    for (int o = 128; o > 0; o >>= 1) { if (tid < o) red[tid] = fmaxf(red[tid], red[tid + o]); __syncthreads(); }
    float mx = red[0]; __syncthreads();
    float e0 = __expf(L[tid] - mx), e1 = __expf(L[tid + 256] - mx);
    red[tid] = e0 + e1; __syncthreads();
    for (int o = 128; o > 0; o >>= 1) { if (tid < o) red[tid] += red[tid + o]; __syncthreads(); }
    float inv = 1.0f / red[0];
    g_attw[br][b][tid] = e0 * inv;
    g_attw[br][b][tid + 256] = e1 * inv;
}

// ---------------- phase 3c: attention-weighted sum ------------------------------
__global__ void k_attsum() {
    int b = blockIdx.x, br = blockIdx.y;
    int d = threadIdx.x;   // 512 threads
    __shared__ float aw[512];
    aw[d] = g_attw[br][b][d];
    __syncthreads();
    int rdh = (d < HDIM) ? (2 * br) : (2 * br + 1);
    int dd = d & 255;
    const float* base = g_HS + (size_t)rdh * SEQ * BATCH * HDIM + (size_t)b * HDIM + dd;
    float a0 = 0.0f, a1 = 0.0f;
    for (int s = 0; s < SEQ; s += 2) {
        a0 = fmaf(aw[s],     base[(size_t)s * BATCH * HDIM], a0);
        a1 = fmaf(aw[s + 1], base[(size_t)(s + 1) * BATCH * HDIM], a1);
    }
    g_ATT[br][b][d] = a0 + a1;
}

// ---------------- phase 4: routed final FC --------------------------------------
__global__ void k_final(const int* __restrict__ z, const float* __restrict__ Wfc,
                        const float* __restrict__ bfc, float* __restrict__ out) {
    int b = blockIdx.x;
    int tid = threadIdx.x;   // 256
    int zb = z[b];
    __shared__ float red0[256], red1[256];
    float a0 = 0.0f, a1 = 0.0f;
    for (int k = tid; k < 1024; k += 256) {
        float v = (k < 512) ? g_ATT[zb + 1][b][k] : g_ATT[0][b][k - 512];
        a0 = fmaf(v, Wfc[k], a0);
        a1 = fmaf(v, Wfc[1024 + k], a1);
    }
    red0[tid] = a0; red1[tid] = a1; __syncthreads();
    for (int o = 128; o > 0; o >>= 1) {
        if (tid < o) { red0[tid] += red0[tid + o]; red1[tid] += red1[tid + o]; }
        __syncthreads();
    }
    if (tid == 0) {
        out[b * 2 + 0] = red0[0] + bfc[0];
        out[b * 2 + 1] = red1[0] + bfc[1];
    }
}

// ---------------- copy general + specifics into d_out ---------------------------
__global__ void k_copyout(float* __restrict__ out) {
    int idx = blockIdx.x * blockDim.x + threadIdx.x;
    const float* A = &g_ATT[0][0][0];
    if (idx < NBR * BATCH * ADIM) out[128 + idx] = A[idx];
}

// ---------------- launcher -------------------------------------------------------
extern "C" void kernel_launch(void* const* d_in, const int* in_sizes, int n_in,
                              void* d_out, int out_size) {
    const int*   x     = (const int*)  d_in[0];
    const int*   z     = (const int*)  d_in[1];
    const float* emb   = (const float*)d_in[2];
    const float* Wih_f = (const float*)d_in[3];
    const float* Whh_f = (const float*)d_in[4];
    const float* bih_f = (const float*)d_in[5];
    const float* bhh_f = (const float*)d_in[6];
    const float* Wih_b = (const float*)d_in[7];
    const float* Whh_b = (const float*)d_in[8];
    const float* bih_b = (const float*)d_in[9];
    const float* bhh_b = (const float*)d_in[10];
    const float* Wa    = (const float*)d_in[11];
    const float* ba    = (const float*)d_in[12];
    const float* watt  = (const float*)d_in[13];
    const float* Wfc   = (const float*)d_in[14];
    const float* bfc   = (const float*)d_in[15];
    float* out = (float*)d_out;

    cudaFuncSetAttribute(k_scan, cudaFuncAttributeMaxDynamicSharedMemorySize, SCAN_SMEM);

    k_init<<<1280, 256>>>();
    k_inputproj<<<dim3(256, 16, 10), 256>>>(x, emb, Wih_f, Wih_b, bih_f, bhh_f, bih_b, bhh_b);
    k_scan<<<80, 256, SCAN_SMEM>>>(Whh_f, Whh_b);
    k_logits<<<dim3(256, 8, 5), 256>>>(Wa, ba, watt);
    k_softmax<<<320, 256>>>();
    k_attsum<<<dim3(64, 5), 512>>>();
    k_final<<<64, 256>>>(z, Wfc, bfc, out);
    k_copyout<<<640, 256>>>(out);
}

// round 9
// speedup vs baseline: 2.7250x; 1.0159x over previous
#include <cuda_runtime.h>
#include <cuda_bf16.h>

#define HDIM   256
#define GDIM   1024      // 4*H
#define BATCH  64
#define SEQ    512
#define NRD    10        // 5 branches * 2 directions
#define NBR    5
#define EDIM   300
#define ADIM   512       // 2*H

typedef unsigned long long ull;
typedef unsigned int u32;

// ---------------- scratch (device globals; no allocation allowed) ----------------
__device__ float g_P [335544320];   // [NRD][SEQ][BATCH][GDIM]
__device__ float g_HS[ 83886080];   // [NRD][SEQ][BATCH][HDIM]
__device__ ull   g_H2[2][NRD][BATCH][HDIM/2];   // h pre-split: (hi bf16x2 | lo bf16x2<<32)
__device__ float g_ATT[NBR][BATCH][ADIM];
__device__ float g_logit[NBR][BATCH][SEQ];
__device__ float g_attw [NBR][BATCH][SEQ];
__device__ unsigned g_cnt[NRD];

__device__ __forceinline__ float fsigm(float x) { return 1.0f / (1.0f + __expf(-x)); }
__device__ __forceinline__ float ftanh(float x) { return 1.0f - 2.0f / (__expf(2.0f * x) + 1.0f); }

// bf16 2-term split of a float pair -> (hi word | lo word << 32)
__device__ __forceinline__ ull split2(float2 v) {
    __nv_bfloat162 h = __floats2bfloat162_rn(v.x, v.y);
    float r0 = v.x - __bfloat162float(h.x);
    float r1 = v.y - __bfloat162float(h.y);
    __nv_bfloat162 l = __floats2bfloat162_rn(r0, r1);
    u32 hw = *(u32*)&h;
    u32 lw = *(u32*)&l;
    return (ull)hw | ((ull)lw << 32);
}

#define MMA_BF16(c, a, b) \
    asm volatile("mma.sync.aligned.m16n8k16.row.col.f32.bf16.bf16.f32 " \
                 "{%0,%1,%2,%3}, {%4,%5,%6,%7}, {%8,%9}, {%0,%1,%2,%3};" \
                 : "+f"((c)[0]), "+f"((c)[1]), "+f"((c)[2]), "+f"((c)[3]) \
                 : "r"((a)[0]), "r"((a)[1]), "r"((a)[2]), "r"((a)[3]), \
                   "r"((b)[0]), "r"((b)[1]))

// ---------------- init -----------------------------------------------------------
__global__ void k_init() {
    int idx = blockIdx.x * blockDim.x + threadIdx.x;
    ull* Hz = &g_H2[0][0][0][0];
    if (idx < 2 * NRD * BATCH * (HDIM / 2)) Hz[idx] = 0ull;
    if (idx < NBR * BATCH * SEQ)            ((float*)g_logit)[idx] = 0.0f;
    if (idx < NRD)                          g_cnt[idx] = 0u;
}

// ---------------- phase 1: P = emb[x] @ Wih.T + (bih+bhh)  [bf16-split HMMA] ------
__global__ void k_inputproj(const int* __restrict__ x, const float* __restrict__ emb,
                            const float* __restrict__ Wih_f, const float* __restrict__ Wih_b,
                            const float* __restrict__ bih_f, const float* __restrict__ bhh_f,
                            const float* __restrict__ bih_b, const float* __restrict__ bhh_b) {
    __shared__ __align__(8) u32 As_s[128 * 20];   // [m][kp*2 + {hi,lo}]
    __shared__ __align__(8) u32 Bs_s[64 * 20];
    __shared__ int tok[128];
    int mtile = blockIdx.x, ntile = blockIdx.y, rd = blockIdx.z;
    int branch = rd >> 1, dir = rd & 1;
    const float* Wih = (dir ? Wih_b : Wih_f) + (size_t)branch * GDIM * EDIM;
    const float* bi  = (dir ? bih_b : bih_f) + branch * GDIM;
    const float* bh  = (dir ? bhh_b : bhh_f) + branch * GDIM;
    int tid = threadIdx.x;
    int m0 = mtile * 128, n0 = ntile * 64;
    if (tid < 128) {
        int m = m0 + tid;
        tok[tid] = x[(m & 63) * SEQ + (m >> 6)];
    }
    int lane = tid & 31, wid = tid >> 5;
    int g = lane >> 2, tg = lane & 3;
    int wm = wid & 3, wn = wid >> 2;
    int mbase = wm * 32, nbase = wn * 32;
    float C[2][4][4];
#pragma unroll
    for (int mt = 0; mt < 2; mt++)
#pragma unroll
        for (int nt = 0; nt < 4; nt++)
#pragma unroll
            for (int q = 0; q < 4; q++) C[mt][nt][q] = 0.0f;
    __syncthreads();

    for (int k0 = 0; k0 < 304; k0 += 16) {
#pragma unroll
        for (int i = 0; i < 4; i++) {
            int task = tid + i * 256;
            int m = task >> 3, kp = task & 7;
            int k = k0 + 2 * kp;
            float2 v = (k < EDIM) ? *(const float2*)(emb + (size_t)tok[m] * EDIM + k)
                                  : make_float2(0.0f, 0.0f);
            *(ull*)&As_s[m * 20 + 2 * kp] = split2(v);
        }
#pragma unroll
        for (int i = 0; i < 2; i++) {
            int task = tid + i * 256;
            int n = task >> 3, kp = task & 7;
            int k = k0 + 2 * kp;
            float2 v = (k < EDIM) ? *(const float2*)(Wih + (size_t)(n0 + n) * EDIM + k)
                                  : make_float2(0.0f, 0.0f);
            *(ull*)&Bs_s[n * 20 + 2 * kp] = split2(v);
        }
        __syncthreads();
        u32 Ahi[2][4], Alo[2][4], Bhi[4][2], Blo[4][2];
#pragma unroll
        for (int mt = 0; mt < 2; mt++) {
            int r0 = mbase + mt * 16 + g;
            ull v0 = *(const ull*)&As_s[r0 * 20 + 2 * tg];
            ull v1 = *(const ull*)&As_s[(r0 + 8) * 20 + 2 * tg];
            ull v2 = *(const ull*)&As_s[r0 * 20 + 2 * (tg + 4)];
            ull v3 = *(const ull*)&As_s[(r0 + 8) * 20 + 2 * (tg + 4)];
            Ahi[mt][0] = (u32)v0; Alo[mt][0] = (u32)(v0 >> 32);
            Ahi[mt][1] = (u32)v1; Alo[mt][1] = (u32)(v1 >> 32);
            Ahi[mt][2] = (u32)v2; Alo[mt][2] = (u32)(v2 >> 32);
            Ahi[mt][3] = (u32)v3; Alo[mt][3] = (u32)(v3 >> 32);
        }
#pragma unroll
        for (int nt = 0; nt < 4; nt++) {
            int n = nbase + nt * 8 + g;
            ull v0 = *(const ull*)&Bs_s[n * 20 + 2 * tg];
            ull v1 = *(const ull*)&Bs_s[n * 20 + 2 * (tg + 4)];
            Bhi[nt][0] = (u32)v0; Blo[nt][0] = (u32)(v0 >> 32);
            Bhi[nt][1] = (u32)v1; Blo[nt][1] = (u32)(v1 >> 32);
        }
#pragma unroll
        for (int mt = 0; mt < 2; mt++)
#pragma unroll
            for (int nt = 0; nt < 4; nt++) {
                MMA_BF16(C[mt][nt], Ahi[mt], Bhi[nt]);
                MMA_BF16(C[mt][nt], Ahi[mt], Blo[nt]);
                MMA_BF16(C[mt][nt], Alo[mt], Bhi[nt]);
            }
        __syncthreads();
    }
#pragma unroll
    for (int mt = 0; mt < 2; mt++)
#pragma unroll
        for (int rr = 0; rr < 2; rr++) {
            int m = m0 + mbase + mt * 16 + g + rr * 8;
            float* Pp = g_P + (((size_t)rd * SEQ + (m >> 6)) * BATCH + (m & 63)) * GDIM + n0 + nbase;
#pragma unroll
            for (int nt = 0; nt < 4; nt++) {
                int nl = nt * 8 + 2 * tg;
                int nf = n0 + nbase + nl;
                float2 o;
                o.x = C[mt][nt][rr * 2 + 0] + bi[nf] + bh[nf];
                o.y = C[mt][nt][rr * 2 + 1] + bi[nf + 1] + bh[nf + 1];
                *(float2*)(Pp + nl) = o;
            }
        }
}

// ---------------- phase 2: persistent recurrent scan  [bf16-split HMMA] -----------
// 80 blocks = 10 recs x 8 j-slices of 32. 8 warps: wm = wid&3 (m16 of batch 64),
// wn = wid>>2 (n64 of 128). Whh rows permuted: n' = wn*64 + 16*gate + jl16 so each
// thread's C fragment holds all 4 gates of its (b, j) units. h pre-split in global.
#define A_CHUNK 1032            // words/chunk: 64 rows * 16 + 8 pad
#define B_CHUNK 2056            // words/chunk: 128 rows * 16 + 8 pad
#define SCAN_SMEM ((16 * A_CHUNK + 16 * B_CHUNK) * 4)   // 197,632 B

__global__ void __launch_bounds__(256, 1)
k_scan(const float* __restrict__ Whh_f, const float* __restrict__ Whh_b) {
    extern __shared__ __align__(16) u32 smw[];
    u32* Bw = smw;                     // Whh split, resident
    u32* Aw = smw + 16 * B_CHUNK;      // h split, restaged per step

    int rd = blockIdx.x >> 3;
    int blk = blockIdx.x & 7;
    int j0 = blk * 32;
    int branch = rd >> 1, dir = rd & 1;
    const float* W = (dir ? Whh_b : Whh_f) + (size_t)branch * GDIM * HDIM;
    int tid = threadIdx.x;
    int lane = tid & 31, wid = tid >> 5;
    int g = lane >> 2, tg = lane & 3;
    int wm = wid & 3, wn = wid >> 2;
    int mbase = wm * 16, nbase = wn * 64;
    int xg = g << 1;                   // xor swizzle key (rows ≡ g mod 8)

    // ---- stage Whh slice (permuted rows, bf16 split), one time ----
    for (int p = tid; p < 128 * 128; p += 256) {
        int r = p >> 7;                 // n' 0..127
        int kpair = p & 127;
        int wnn = r >> 6, w = r & 63;
        int gate = w >> 4, jl = wnn * 16 + (w & 15);
        float2 v = *(const float2*)&W[(size_t)(gate * HDIM + j0 + jl) * HDIM + 2 * kpair];
        int idx = (kpair >> 3) * B_CHUNK + r * 16 + ((2 * (kpair & 7)) ^ ((r & 7) << 1));
        *(ull*)&Bw[idx] = split2(v);
    }
    float c[2][4];                      // [rr][jh*2+q]
#pragma unroll
    for (int a = 0; a < 2; a++)
#pragma unroll
        for (int b = 0; b < 4; b++) c[a][b] = 0.0f;
    __syncthreads();

    for (int t = 0; t < SEQ; ++t) {
        int sidx = dir ? (SEQ - 1 - t) : t;
        // prefetch P preacts for this thread's 32 output units
        const float* Pb = g_P + ((size_t)rd * SEQ + sidx) * BATCH * GDIM;
        float2 Pr[2][2][4];             // [rr][jh][gate]
#pragma unroll
        for (int rr = 0; rr < 2; rr++) {
            int b = mbase + g + 8 * rr;
#pragma unroll
            for (int jh = 0; jh < 2; jh++) {
                int j = j0 + wn * 16 + jh * 8 + 2 * tg;
#pragma unroll
                for (int gate = 0; gate < 4; gate++)
                    Pr[rr][jh][gate] = *(const float2*)&Pb[(size_t)b * GDIM + gate * HDIM + j];
            }
        }

        // stage h (pre-split in global -> no math) into Aw
        int par = t & 1;
        const ull* Hs = &g_H2[par][rd][0][0];
#pragma unroll
        for (int i = 0; i < 32; i++) {
            int p = tid + i * 256;
            int b = p >> 7, kpair = p & 127;
            ull v = __ldcv(&Hs[b * 128 + kpair]);
            int idx = (kpair >> 3) * A_CHUNK + b * 16 + ((2 * (kpair & 7)) ^ ((b & 7) << 1));
            *(ull*)&Aw[idx] = v;
        }
        __syncthreads();

        float C[8][4];
#pragma unroll
        for (int nt = 0; nt < 8; nt++)
#pragma unroll
            for (int q = 0; q < 4; q++) C[nt][q] = 0.0f;

#pragma unroll 4
        for (int chunk = 0; chunk < 16; chunk++) {
            const u32* Ac = Aw + chunk * A_CHUNK;
            const u32* Bc = Bw + chunk * B_CHUNK;
            u32 Ahi[4], Alo[4];
            {
                int r0 = mbase + g;
                ull v0 = *(const ull*)&Ac[r0 * 16 + ((2 * tg) ^ xg)];
                ull v1 = *(const ull*)&Ac[(r0 + 8) * 16 + ((2 * tg) ^ xg)];
                ull v2 = *(const ull*)&Ac[r0 * 16 + ((2 * (tg + 4)) ^ xg)];
                ull v3 = *(const ull*)&Ac[(r0 + 8) * 16 + ((2 * (tg + 4)) ^ xg)];
                Ahi[0] = (u32)v0; Alo[0] = (u32)(v0 >> 32);
                Ahi[1] = (u32)v1; Alo[1] = (u32)(v1 >> 32);
                Ahi[2] = (u32)v2; Alo[2] = (u32)(v2 >> 32);
                Ahi[3] = (u32)v3; Alo[3] = (u32)(v3 >> 32);
            }
#pragma unroll
            for (int nt = 0; nt < 8; nt++) {
                int n = nbase + nt * 8 + g;
                ull v0 = *(const ull*)&Bc[n * 16 + ((2 * tg) ^ xg)];
                ull v1 = *(const ull*)&Bc[n * 16 + ((2 * (tg + 4)) ^ xg)];
                u32 Bhi[2], Blo[2];
                Bhi[0] = (u32)v0; Blo[0] = (u32)(v0 >> 32);
                Bhi[1] = (u32)v1; Blo[1] = (u32)(v1 >> 32);
                MMA_BF16(C[nt], Ahi, Bhi);
                MMA_BF16(C[nt], Ahi, Blo);
                MMA_BF16(C[nt], Alo, Bhi);
            }
        }

        // epilogue: gates + cell update, register-local; h stored pre-split
        float* HSo = g_HS + ((size_t)rd * SEQ + sidx) * BATCH * HDIM;
        ull* Hn = &g_H2[par ^ 1][rd][0][0];
#pragma unroll
        for (int rr = 0; rr < 2; rr++) {
            int b = mbase + g + 8 * rr;
#pragma unroll
            for (int jh = 0; jh < 2; jh++) {
                int j = j0 + wn * 16 + jh * 8 + 2 * tg;
                float iv0 = C[0 + jh][rr * 2 + 0] + Pr[rr][jh][0].x;
                float fv0 = C[2 + jh][rr * 2 + 0] + Pr[rr][jh][1].x;
                float gv0 = C[4 + jh][rr * 2 + 0] + Pr[rr][jh][2].x;
                float ov0 = C[6 + jh][rr * 2 + 0] + Pr[rr][jh][3].x;
                float iv1 = C[0 + jh][rr * 2 + 1] + Pr[rr][jh][0].y;
                float fv1 = C[2 + jh][rr * 2 + 1] + Pr[rr][jh][1].y;
                float gv1 = C[4 + jh][rr * 2 + 1] + Pr[rr][jh][2].y;
                float ov1 = C[6 + jh][rr * 2 + 1] + Pr[rr][jh][3].y;
                float cn0 = fsigm(fv0) * c[rr][jh * 2 + 0] + fsigm(iv0) * ftanh(gv0);
                float cn1 = fsigm(fv1) * c[rr][jh * 2 + 1] + fsigm(iv1) * ftanh(gv1);
                c[rr][jh * 2 + 0] = cn0;
                c[rr][jh * 2 + 1] = cn1;
                float2 hv;
                hv.x = fsigm(ov0) * ftanh(cn0);
                hv.y = fsigm(ov1) * ftanh(cn1);
                Hn[b * 128 + (j >> 1)] = split2(hv);
                *(float2*)&HSo[(size_t)b * HDIM + j] = hv;
            }
        }
        // inter-block step barrier: bar -> release-red -> acquire-poll (no membar.gl)
        __syncthreads();
        if (tid == 0) {
            asm volatile("red.release.gpu.global.add.u32 [%0], %1;"
                         :: "l"(&g_cnt[rd]), "r"(1u) : "memory");
            unsigned target = 8u * (unsigned)(t + 1), v;
            do {
                asm volatile("ld.acquire.gpu.global.u32 %0, [%1];"
                             : "=r"(v) : "l"(&g_cnt[rd]) : "memory");
            } while (v < target);
        }
        __syncthreads();
    }
}

// ---------------- phase 3a: attention logits  [bf16-split HMMA, fused tanh+watt] --
__global__ void k_logits(const float* __restrict__ Wa, const float* __restrict__ ba,
                         const float* __restrict__ watt) {
    __shared__ __align__(8) u32 As_s[128 * 20];
    __shared__ __align__(8) u32 Bs_s[64 * 20];
    int mtile = blockIdx.x, ntile = blockIdx.y, br = blockIdx.z;
    const float* W = Wa + (size_t)br * ADIM * ADIM;
    int tid = threadIdx.x;
    int m0 = mtile * 128, n0 = ntile * 64;
    int lane = tid & 31, wid = tid >> 5;
    int g = lane >> 2, tg = lane & 3;
    int wm = wid & 3, wn = wid >> 2;
    int mbase = wm * 32, nbase = wn * 32;
    float C[2][4][4];
#pragma unroll
    for (int mt = 0; mt < 2; mt++)
#pragma unroll
        for (int nt = 0; nt < 4; nt++)
#pragma unroll
            for (int q = 0; q < 4; q++) C[mt][nt][q] = 0.0f;

    for (int k0 = 0; k0 < ADIM; k0 += 16) {
#pragma unroll
        for (int i = 0; i < 4; i++) {
            int task = tid + i * 256;
            int m = task >> 3, kp = task & 7;
            int k = k0 + 2 * kp;
            int mm = m0 + m;
            int rdh = 2 * br + (k >> 8);
            float2 v = *(const float2*)(g_HS + (((size_t)rdh * SEQ + (mm >> 6)) * BATCH + (mm & 63)) * HDIM + (k & 255));
            *(ull*)&As_s[m * 20 + 2 * kp] = split2(v);
        }
#pragma unroll
        for (int i = 0; i < 2; i++) {
            int task = tid + i * 256;
            int n = task >> 3, kp = task & 7;
            float2 v = *(const float2*)(W + (size_t)(n0 + n) * ADIM + k0 + 2 * kp);
            *(ull*)&Bs_s[n * 20 + 2 * kp] = split2(v);
        }
        __syncthreads();
        u32 Ahi[2][4], Alo[2][4], Bhi[4][2], Blo[4][2];
#pragma unroll
        for (int mt = 0; mt < 2; mt++) {
            int r0 = mbase + mt * 16 + g;
            ull v0 = *(const ull*)&As_s[r0 * 20 + 2 * tg];
            ull v1 = *(const ull*)&As_s[(r0 + 8) * 20 + 2 * tg];
            ull v2 = *(const ull*)&As_s[r0 * 20 + 2 * (tg + 4)];
            ull v3 = *(const ull*)&As_s[(r0 + 8) * 20 + 2 * (tg + 4)];
            Ahi[mt][0] = (u32)v0; Alo[mt][0] = (u32)(v0 >> 32);
            Ahi[mt][1] = (u32)v1; Alo[mt][1] = (u32)(v1 >> 32);
            Ahi[mt][2] = (u32)v2; Alo[mt][2] = (u32)(v2 >> 32);
            Ahi[mt][3] = (u32)v3; Alo[mt][3] = (u32)(v3 >> 32);
        }
#pragma unroll
        for (int nt = 0; nt < 4; nt++) {
            int n = nbase + nt * 8 + g;
            ull v0 = *(const ull*)&Bs_s[n * 20 + 2 * tg];
            ull v1 = *(const ull*)&Bs_s[n * 20 + 2 * (tg + 4)];
            Bhi[nt][0] = (u32)v0; Blo[nt][0] = (u32)(v0 >> 32);
            Bhi[nt][1] = (u32)v1; Blo[nt][1] = (u32)(v1 >> 32);
        }
#pragma unroll
        for (int mt = 0; mt < 2; mt++)
#pragma unroll
            for (int nt = 0; nt < 4; nt++) {
                MMA_BF16(C[mt][nt], Ahi[mt], Bhi[nt]);
                MMA_BF16(C[mt][nt], Ahi[mt], Blo[nt]);
                MMA_BF16(C[mt][nt], Alo[mt], Bhi[nt]);
            }
        __syncthreads();
    }
#pragma unroll
    for (int mt = 0; mt < 2; mt++) {
        float p0 = 0.0f, p1 = 0.0f;
#pragma unroll
        for (int nt = 0; nt < 4; nt++) {
            int nf = n0 + nbase + nt * 8 + 2 * tg;
            float b0 = ba[br * ADIM + nf], w0 = watt[br * ADIM + nf];
            float b1 = ba[br * ADIM + nf + 1], w1 = watt[br * ADIM + nf + 1];
            p0 += ftanh(C[mt][nt][0] + b0) * w0 + ftanh(C[mt][nt][1] + b1) * w1;
            p1 += ftanh(C[mt][nt][2] + b0) * w0 + ftanh(C[mt][nt][3] + b1) * w1;
        }
        p0 += __shfl_xor_sync(0xffffffffu, p0, 1);
        p0 += __shfl_xor_sync(0xffffffffu, p0, 2);
        p1 += __shfl_xor_sync(0xffffffffu, p1, 1);
        p1 += __shfl_xor_sync(0xffffffffu, p1, 2);
        if (tg == 0) {
            int m = m0 + mbase + mt * 16 + g;
            atomicAdd(&g_logit[br][m & 63][m >> 6], p0);
            int m2 = m + 8;
            atomicAdd(&g_logit[br][m2 & 63][m2 >> 6], p1);
        }
    }
}

// ---------------- phase 3b: softmax over S -------------------------------------
__global__ void k_softmax() {
    int br = blockIdx.x >> 6, b = blockIdx.x & 63;
    __shared__ float red[256];
    const float* L = &g_logit[br][b][0];
    int tid = threadIdx.x;
    red[tid] = fmaxf(L[tid], L[tid + 256]); __syncthreads();
    for (int o = 128; o > 0; o >>= 1) { if (tid < o) red[tid] = fmaxf(red[tid], red[tid + o]); __syncthreads(); }
    float mx = red[0]; __syncthreads();
    float e0 = __expf(L[tid] - mx), e1 = __expf(L[tid + 256] - mx);
    red[tid] = e0 + e1; __syncthreads();
    for (int o = 128; o > 0; o >>= 1) { if (tid < o) red[tid] += red[tid + o]; __syncthreads(); }
    float inv = 1.0f / red[0];
    g_attw[br][b][tid] = e0 * inv;
    g_attw[br][b][tid + 256] = e1 * inv;
}

// ---------------- phase 3c: attention-weighted sum ------------------------------
__global__ void k_attsum() {
    int b = blockIdx.x, br = blockIdx.y;
    int d = threadIdx.x;
    __shared__ float aw[512];
    aw[d] = g_attw[br][b][d];
    __syncthreads();
    int rdh = (d < HDIM) ? (2 * br) : (2 * br + 1);
    const float* base = g_HS + (size_t)rdh * SEQ * BATCH * HDIM + (size_t)b * HDIM + (d & 255);
    float a0 = 0.0f, a1 = 0.0f;
    for (int s = 0; s < SEQ; s += 2) {
        a0 = fmaf(aw[s],     base[(size_t)s * BATCH * HDIM], a0);
        a1 = fmaf(aw[s + 1], base[(size_t)(s + 1) * BATCH * HDIM], a1);
    }
    g_ATT[br][b][d] = a0 + a1;
}

// ---------------- phase 4: routed final FC --------------------------------------
__global__ void k_final(const int* __restrict__ z, const float* __restrict__ Wfc,
                        const float* __restrict__ bfc, float* __restrict__ out) {
    int b = blockIdx.x;
    int tid = threadIdx.x;
    int zb = z[b];
    __shared__ float red0[256], red1[256];
    float a0 = 0.0f, a1 = 0.0f;
    for (int k = tid; k < 1024; k += 256) {
        float v = (k < 512) ? g_ATT[zb + 1][b][k] : g_ATT[0][b][k - 512];
        a0 = fmaf(v, Wfc[k], a0);
        a1 = fmaf(v, Wfc[1024 + k], a1);
    }
    red0[tid] = a0; red1[tid] = a1; __syncthreads();
    for (int o = 128; o > 0; o >>= 1) {
        if (tid < o) { red0[tid] += red0[tid + o]; red1[tid] += red1[tid + o]; }
        __syncthreads();
    }
    if (tid == 0) {
        out[b * 2 + 0] = red0[0] + bfc[0];
        out[b * 2 + 1] = red1[0] + bfc[1];
    }
}

// ---------------- copy general + specifics into d_out ---------------------------
__global__ void k_copyout(float* __restrict__ out) {
    int idx = blockIdx.x * blockDim.x + threadIdx.x;
    if (idx < NBR * BATCH * ADIM) out[128 + idx] = (&g_ATT[0][0][0])[idx];
}

// ---------------- launcher -------------------------------------------------------
extern "C" void kernel_launch(void* const* d_in, const int* in_sizes, int n_in,
                              void* d_out, int out_size) {
    const int*   x     = (const int*)  d_in[0];
    const int*   z     = (const int*)  d_in[1];
    const float* emb   = (const float*)d_in[2];
    const float* Wih_f = (const float*)d_in[3];
    const float* Whh_f = (const float*)d_in[4];
    const float* bih_f = (const float*)d_in[5];
    const float* bhh_f = (const float*)d_in[6];
    const float* Wih_b = (const float*)d_in[7];
    const float* Whh_b = (const float*)d_in[8];
    const float* bih_b = (const float*)d_in[9];
    const float* bhh_b = (const float*)d_in[10];
    const float* Wa    = (const float*)d_in[11];
    const float* ba    = (const float*)d_in[12];
    const float* watt  = (const float*)d_in[13];
    const float* Wfc   = (const float*)d_in[14];
    const float* bfc   = (const float*)d_in[15];
    float* out = (float*)d_out;

    cudaFuncSetAttribute(k_scan, cudaFuncAttributeMaxDynamicSharedMemorySize, SCAN_SMEM);

    k_init<<<1280, 256>>>();
    k_inputproj<<<dim3(256, 16, 10), 256>>>(x, emb, Wih_f, Wih_b, bih_f, bhh_f, bih_b, bhh_b);
    k_scan<<<80, 256, SCAN_SMEM>>>(Whh_f, Whh_b);
    k_logits<<<dim3(256, 8, 5), 256>>>(Wa, ba, watt);
    k_softmax<<<320, 256>>>();
    k_attsum<<<dim3(64, 5), 512>>>();
    k_final<<<64, 256>>>(z, Wfc, bfc, out);
    k_copyout<<<640, 256>>>(out);
}